// round 13
// baseline (speedup 1.0000x reference)
#include <cuda_runtime.h>
#include <cuda_fp16.h>
#include <math.h>
#include <stdint.h>

#define SCALE 0.088388347648318447f  // 1/sqrt(128)

// ---- static scratch (allocation-free), fp16 intermediates ----
__device__ __half g_K  [16777216];   // [b,h,j,d]
__device__ __half g_Vt [16777216];   // [b,h,d,j]
__device__ __half g_QU [8388608];    // [b,h,i,d]  q+u
__device__ __half g_QV [8388608];    // [b,h,i,d]  q+v
__device__ __half g_P  [1048576];    // [h,jj,d]
__device__ __half g_S2 [67108864];   // [bh,i,j]   shifted position scores (valid j<=i+512)
__device__ __half g_O  [8388608];    // [i*B+b, h*128+d]
__device__ float  g_PE [131072];     // [jj,e]

__global__ void pe_fill() {
    int idx = blockIdx.x * blockDim.x + threadIdx.x;
    if (idx >= 65536) return;
    int jj = idx >> 6, e2 = idx & 63;
    double pos  = (double)(1023 - jj);
    double invf = exp(-((double)e2 / 64.0) * log(10000.0));
    double ang  = pos * invf;
    g_PE[jj * 128 + e2]      = (float)sin(ang);
    g_PE[jj * 128 + 64 + e2] = (float)cos(ang);
}

__device__ __forceinline__ uint32_t f2h2(float a, float b) {
    __half2 h = __floats2half2_rn(a, b);
    return *reinterpret_cast<uint32_t*>(&h);
}
__device__ __forceinline__ void ldsm4(uint32_t& r0, uint32_t& r1, uint32_t& r2, uint32_t& r3, uint32_t addr) {
    asm volatile("ldmatrix.sync.aligned.m8n8.x4.shared.b16 {%0,%1,%2,%3}, [%4];"
                 : "=r"(r0), "=r"(r1), "=r"(r2), "=r"(r3) : "r"(addr));
}
__device__ __forceinline__ void mma16(float* c, const uint32_t* a, uint32_t b0, uint32_t b1) {
    asm volatile("mma.sync.aligned.m16n8k16.row.col.f32.f16.f16.f32 "
                 "{%0,%1,%2,%3},{%4,%5,%6,%7},{%8,%9},{%0,%1,%2,%3};"
                 : "+f"(c[0]), "+f"(c[1]), "+f"(c[2]), "+f"(c[3])
                 : "r"(a[0]), "r"(a[1]), "r"(a[2]), "r"(a[3]), "r"(b0), "r"(b1));
}
__device__ __forceinline__ void cpa16(uint32_t saddr, const void* gptr) {
    asm volatile("cp.async.cg.shared.global [%0], [%1], 16;" :: "r"(saddr), "l"(gptr));
}
__device__ __forceinline__ void cp_commit() { asm volatile("cp.async.commit_group;"); }
template<int N> __device__ __forceinline__ void cp_wait() { asm volatile("cp.async.wait_group %0;" :: "n"(N)); }

// ---- fp16 tensor-core NT GEMM: C[M,N] = A[M,K] * W[N,K]^T ----
// BM=128, BN=64, BK=64 halves; 8 warps, each 32x32 via m16n8k16.
// K=128 modes (0,1,2,4): B resident in smem (both K-chunks), CTA loops over MI m-tiles
// with A double-buffered continuously (fill paid once per CTA, B loads amortized MI x).
// MODE 6 (K=1024): classic double-buffered path.
template<int MODE, int MI>
__global__ void __launch_bounds__(256, 2) gemm_k(
    const float* __restrict__ inputs, const float* __restrict__ mem0,
    const float* __restrict__ Wext, const float* __restrict__ uu,
    const float* __restrict__ vv, float* __restrict__ dout, int writeAux)
{
    constexpr int K   = (MODE >= 5) ? 1024 : 128;  // elements
    constexpr int KIT = K / 64;
    constexpr bool AF32 = (MODE <= 2);
    constexpr bool BF32 = (MODE <= 2 || MODE == 6);
    const int z  = blockIdx.z;
    const int mbase = blockIdx.y * (128 * MI), n0 = blockIdx.x * 64;
    if (MODE == 4 && mbase + n0 + 190 < 511) return;  // fully outside used band
    const int tid = threadIdx.x;
    const int lane = tid & 31, w = tid >> 5;
    const int wm = w >> 1, wn = w & 1;

    const float* Af = nullptr;
    const __half* Ah = nullptr;
    const float* Bf = Wext;
    const __half* Bh = nullptr;
    if (MODE == 1) Af = inputs;
    if (MODE == 2) Af = g_PE;
    if (MODE == 4) { Ah = g_QV + (size_t)z * 65536;  Bh = g_P + (size_t)(z & 7) * 131072; }
    if (MODE == 6) { Ah = g_O; }

    __shared__ uint32_t As[2][4096];
    __shared__ uint32_t Bs[2][2048];
    uint32_t as_addr = (uint32_t)__cvta_generic_to_shared(As);
    uint32_t bs_addr = (uint32_t)__cvta_generic_to_shared(Bs);

    float4 pa32[4][2], pb32[2][2];
    uint4 pa16[4], pb16[2];

    // loadA: rows rowBase..rowBase+127, K-chunk kc (64 halves)
    auto loadA = [&](int rowBase, int kc) {
#pragma unroll
        for (int i = 0; i < 4; ++i) {
            int idx = tid + i * 256;
            int row = idx >> 3, ch = idx & 7;
            int r = rowBase + row;
            if (AF32) {
                const float* Ap;
                if (MODE == 0)
                    Ap = (r < 8192) ? (mem0 + (size_t)r * 128)
                                    : (inputs + (size_t)(r - 8192) * 128);
                else
                    Ap = Af + (size_t)r * K;
                pa32[i][0] = *(const float4*)(Ap + kc * 64 + ch * 8);
                pa32[i][1] = *(const float4*)(Ap + kc * 64 + ch * 8 + 4);
            } else {
                pa16[i] = *(const uint4*)(Ah + (size_t)r * K + kc * 64 + ch * 8);
            }
        }
    };
    auto loadB = [&](int kc) {
#pragma unroll
        for (int i = 0; i < 2; ++i) {
            int idx = tid + i * 256;
            int row = idx >> 3, ch = idx & 7;
            if (BF32) {
                pb32[i][0] = *(const float4*)(Bf + (size_t)(n0 + row) * K + kc * 64 + ch * 8);
                pb32[i][1] = *(const float4*)(Bf + (size_t)(n0 + row) * K + kc * 64 + ch * 8 + 4);
            } else {
                pb16[i] = *(const uint4*)(Bh + (size_t)(n0 + row) * K + kc * 64 + ch * 8);
            }
        }
    };
    auto stageA = [&](int s) {
#pragma unroll
        for (int i = 0; i < 4; ++i) {
            int idx = tid + i * 256;
            int row = idx >> 3, ch = idx & 7;
            uint32_t off = row * 32 + ((ch ^ (row & 7)) << 2);
            uint4 v;
            if (AF32) v = make_uint4(f2h2(pa32[i][0].x, pa32[i][0].y), f2h2(pa32[i][0].z, pa32[i][0].w),
                                     f2h2(pa32[i][1].x, pa32[i][1].y), f2h2(pa32[i][1].z, pa32[i][1].w));
            else v = pa16[i];
            *(uint4*)&As[s][off] = v;
        }
    };
    auto stageB = [&](int s) {
#pragma unroll
        for (int i = 0; i < 2; ++i) {
            int idx = tid + i * 256;
            int row = idx >> 3, ch = idx & 7;
            uint32_t off = row * 32 + ((ch ^ (row & 7)) << 2);
            uint4 v;
            if (BF32) v = make_uint4(f2h2(pb32[i][0].x, pb32[i][0].y), f2h2(pb32[i][0].z, pb32[i][0].w),
                                     f2h2(pb32[i][1].x, pb32[i][1].y), f2h2(pb32[i][1].z, pb32[i][1].w));
            else v = pb16[i];
            *(uint4*)&Bs[s][off] = v;
        }
    };

    const int lrow = lane & 7, lm = lane >> 3;
    const int r0l = lane >> 2, c0l = (lane & 3) * 2;

    // epilogue for one 128-row m-tile
    auto epilogue = [&](int m0, float (*acc)[4][4]) {
#pragma unroll
        for (int mi2 = 0; mi2 < 2; ++mi2)
#pragma unroll
            for (int nj = 0; nj < 4; ++nj)
#pragma unroll
                for (int e = 0; e < 4; ++e) {
                    int r = m0 + wm * 32 + mi2 * 16 + r0l + ((e >= 2) ? 8 : 0);
                    int n = n0 + wn * 32 + nj * 8 + c0l + (e & 1);
                    float val = acc[mi2][nj][e];
                    if (MODE == 0) {
                        int j = r >> 4, b = r & 15;
                        if (n < 1024) {
                            int h = n >> 7, d = n & 127;
                            g_K[(size_t)((b * 8 + h) * 1024 + j) * 128 + d] = __float2half(val);
                        } else {
                            int n2 = n - 1024; int h = n2 >> 7, d = n2 & 127;
                            g_Vt[(size_t)((b * 8 + h) * 128 + d) * 1024 + j] = __float2half(val);
                        }
                    } else if (MODE == 1) {
                        int i = r >> 4, b = r & 15;
                        size_t base = (size_t)((b * 8 + (n >> 7)) * 512 + i) * 128 + (n & 127);
                        g_QU[base] = __float2half(val + uu[n]);
                        g_QV[base] = __float2half(val + vv[n]);
                    } else if (MODE == 2) {
                        g_P[(size_t)((n >> 7) * 1024 + r) * 128 + (n & 127)] = __float2half(val);
                    } else if (MODE == 4) {
                        int j = n - 511 + r;  // rel-shift: S2shift[i][j] = S2[i][511+j-i]
                        if (j >= 0 && j < 1024)
                            g_S2[(size_t)z * 524288 + (size_t)r * 1024 + j] = __float2half(val);
                    } else {  // MODE 6
                        dout[(size_t)r * 128 + n] = val;
                        if (writeAux) dout[2097152 + (size_t)r * 128 + n] = val;
                    }
                }
    };

    // one 64-K MMA block: A fragments from As[sa], B fragments from Bs[sb]
    auto mmaBlock = [&](int sa, int sb, float (*acc)[4][4]) {
#pragma unroll
        for (int ks = 0; ks < 4; ++ks) {
            uint32_t afr[2][4], bfr[2][4];
#pragma unroll
            for (int mi2 = 0; mi2 < 2; ++mi2) {
                int row = wm * 32 + mi2 * 16 + ((lm & 1) << 3) + lrow;
                int ch  = ks * 2 + (lm >> 1);
                ldsm4(afr[mi2][0], afr[mi2][1], afr[mi2][2], afr[mi2][3],
                      as_addr + ((sa * 4096 + row * 32 + ((ch ^ lrow) << 2)) << 2));
            }
#pragma unroll
            for (int np = 0; np < 2; ++np) {
                int row = wn * 32 + np * 16 + ((lm >> 1) << 3) + lrow;
                int ch  = ks * 2 + (lm & 1);
                ldsm4(bfr[np][0], bfr[np][1], bfr[np][2], bfr[np][3],
                      bs_addr + ((sb * 2048 + row * 32 + ((ch ^ lrow) << 2)) << 2));
            }
#pragma unroll
            for (int mi2 = 0; mi2 < 2; ++mi2)
#pragma unroll
                for (int nj = 0; nj < 4; ++nj)
                    mma16(acc[mi2][nj], afr[mi2], bfr[nj >> 1][(nj & 1) * 2], bfr[nj >> 1][(nj & 1) * 2 + 1]);
        }
    };

    if constexpr (MODE >= 5) {
        // ---- classic path (K=1024): A and B double-buffered per K-iter ----
        float acc[2][4][4];
#pragma unroll
        for (int a = 0; a < 2; ++a)
#pragma unroll
            for (int b = 0; b < 4; ++b)
#pragma unroll
                for (int c = 0; c < 4; ++c) acc[a][b][c] = 0.f;
        loadA(mbase, 0); loadB(0);
        stageA(0); stageB(0);
        __syncthreads();
        for (int it = 0; it < KIT; ++it) {
            const int s = it & 1;
            if (it + 1 < KIT) { loadA(mbase, it + 1); loadB(it + 1); }
            mmaBlock(s, s, acc);
            if (it + 1 < KIT) { stageA(s ^ 1); stageB(s ^ 1); __syncthreads(); }
        }
        epilogue(mbase, acc);
    } else {
        // ---- B-resident path (K=128): B chunks 0,1 loaded once; A streams over MI m-tiles ----
        loadB(0); stageB(0);
        loadB(1); stageB(1);
        loadA(mbase, 0);
        stageA(0);
        __syncthreads();
        for (int mi = 0; mi < MI; ++mi) {
            const int m0 = mbase + mi * 128;
            float acc[2][4][4];
#pragma unroll
            for (int a = 0; a < 2; ++a)
#pragma unroll
                for (int b = 0; b < 4; ++b)
#pragma unroll
                    for (int c = 0; c < 4; ++c) acc[a][b][c] = 0.f;
#pragma unroll
            for (int k = 0; k < 2; ++k) {
                const int step = mi * 2 + k;
                const int s = step & 1;
                const bool hn = (step + 1 < MI * 2);
                if (hn) loadA((k == 0) ? m0 : m0 + 128, k ^ 1);
                mmaBlock(s, k, acc);
                if (hn) { stageA(s ^ 1); __syncthreads(); }
            }
            epilogue(m0, acc);
        }
    }
}

// ---- fused flash attention (fp16): 64-row CTAs, 128 threads, 2 CTAs/SM ----
// S = QK^T + S2shift, masked online softmax, O = P V.
// K, V, S2 tiles double-buffered via cp.async: jt+1 loads overlap jt compute.
// Per stage (10240 u32): K at +0 (2 segs x 2048), V at +4096, S2 at +8192 (64 rows).
__global__ void __launch_bounds__(128, 2) flash_k() {
    extern __shared__ uint32_t sm[];
    uint32_t* sP = sm + 20480;     // 64 i-rows x 32 u32
    const uint32_t smb = (uint32_t)__cvta_generic_to_shared(sm);
    const uint32_t sPb = (uint32_t)__cvta_generic_to_shared(sP);

    const int bh = blockIdx.y;
    const int ix = 7 - blockIdx.x;     // heavy tiles launch first
    const int i0 = ix * 64;
    const int tid = threadIdx.x, lane = tid & 31, w = tid >> 5;  // w in 0..3
    const int lrow = lane & 7, lm = lane >> 3;
    const int r0l = lane >> 2, c0l = (lane & 3) * 2;

    const __half* Qb  = g_QU + (size_t)bh * 65536;
    const __half* Kb  = g_K  + (size_t)bh * 131072;
    const __half* Vb  = g_Vt + (size_t)bh * 131072;
    const __half* S2b = g_S2 + (size_t)bh * 524288;

    uint32_t qf[8][4];

    // ---- Q fragments via smem staging (single 64-row pass into stage-0 K region) ----
#pragma unroll
    for (int t = 0; t < 8; ++t) {
        int idx = tid + t * 128;
        int row = idx >> 4, c16 = idx & 15;
        int seg = c16 >> 3, ch = c16 & 7;
        uint4 v = *(const uint4*)(Qb + (size_t)(i0 + row) * 128 + c16 * 8);
        *(uint4*)&sm[seg * 2048 + row * 32 + ((ch ^ (row & 7)) << 2)] = v;
    }
    __syncthreads();
    {
        int wr = w * 16;
#pragma unroll
        for (int ks = 0; ks < 8; ++ks) {
            int row = wr + ((lm & 1) << 3) + lrow;
            int seg = ks >> 2, ch = (ks & 3) * 2 + (lm >> 1);
            ldsm4(qf[ks][0], qf[ks][1], qf[ks][2], qf[ks][3],
                  smb + ((seg * 2048 + row * 32 + ((ch ^ lrow) << 2)) << 2));
        }
    }
    __syncthreads();

    // cp.async prefetch of one jt tile (K 16KB + V 16KB + S2 8KB) into stage s
    auto pref = [&](int jt, int s) {
        int j0 = jt * 64;
        int sb = s * 10240;
#pragma unroll
        for (int t = 0; t < 8; ++t) {
            int idx = tid + t * 128;
            int row = idx >> 4, c16 = idx & 15;
            int seg = c16 >> 3, ch = c16 & 7;
            cpa16(smb + ((sb + seg * 2048 + row * 32 + ((ch ^ (row & 7)) << 2)) << 2),
                  Kb + (size_t)(j0 + row) * 128 + c16 * 8);
        }
#pragma unroll
        for (int t = 0; t < 8; ++t) {
            int idx = tid + t * 128;
            int row = idx >> 3, ch = idx & 7;
            cpa16(smb + ((sb + 4096 + row * 32 + ((ch ^ (row & 7)) << 2)) << 2),
                  Vb + (size_t)row * 1024 + j0 + ch * 8);
        }
#pragma unroll
        for (int t = 0; t < 4; ++t) {
            int idx = tid + t * 128;
            int row = idx >> 3, ch = idx & 7;
            cpa16(smb + ((sb + 8192 + row * 32 + ((ch ^ (row & 7)) << 2)) << 2),
                  S2b + (size_t)(i0 + row) * 1024 + j0 + ch * 8);
        }
    };

    float of[16][4];
#pragma unroll
    for (int a = 0; a < 16; ++a)
#pragma unroll
        for (int e = 0; e < 4; ++e) of[a][e] = 0.f;
    float mrow0 = -1e30f, mrow1 = -1e30f;
    float lrow0 = 0.f, lrow1 = 0.f;

    const int gi0 = i0 + w * 16 + r0l;
    const int gi1 = gi0 + 8;
    const int lr0 = w * 16 + r0l, lr1 = lr0 + 8;  // local rows in sS2/sP (0..63)
    const int njt = ix + 9;       // covers j <= i0+63+512

    pref(0, 0); cp_commit();

    for (int jt = 0; jt < njt; ++jt) {
        const int s = jt & 1;
        int j0 = jt * 64;
        if (jt + 1 < njt) { pref(jt + 1, s ^ 1); cp_commit(); cp_wait<1>(); }
        else cp_wait<0>();
        __syncthreads();
        const int sb = s * 10240;

        // scores: S = Q K^T (16 x 64 per warp)
        float sacc[8][4];
#pragma unroll
        for (int a = 0; a < 8; ++a)
#pragma unroll
            for (int e = 0; e < 4; ++e) sacc[a][e] = 0.f;
#pragma unroll
        for (int ks = 0; ks < 8; ++ks) {
            uint32_t bfr[4][4];
#pragma unroll
            for (int nb = 0; nb < 4; ++nb) {
                int row = nb * 16 + ((lm >> 1) << 3) + lrow;
                int seg = ks >> 2, ch = (ks & 3) * 2 + (lm & 1);
                ldsm4(bfr[nb][0], bfr[nb][1], bfr[nb][2], bfr[nb][3],
                      smb + ((sb + seg * 2048 + row * 32 + ((ch ^ lrow) << 2)) << 2));
            }
#pragma unroll
            for (int nf = 0; nf < 8; ++nf)
                mma16(sacc[nf], qf[ks], bfr[nf >> 1][(nf & 1) * 2], bfr[nf >> 1][(nf & 1) * 2 + 1]);
        }

        // add shifted position scores (smem), mask, scale, online softmax
        float mnew0 = mrow0, mnew1 = mrow1;
#pragma unroll
        for (int nf = 0; nf < 8; ++nf) {
            int jc = j0 + nf * 8 + c0l;
            uint32_t u0 = sm[sb + 8192 + lr0 * 32 + ((nf ^ r0l) << 2) + (lane & 3)];
            uint32_t u1 = sm[sb + 8192 + lr1 * 32 + ((nf ^ r0l) << 2) + (lane & 3)];
            float2 p0 = __half22float2(*reinterpret_cast<__half2*>(&u0));
            float2 p1 = __half22float2(*reinterpret_cast<__half2*>(&u1));
            float s00 = (sacc[nf][0] + p0.x) * SCALE;
            float s01 = (sacc[nf][1] + p0.y) * SCALE;
            float s10 = (sacc[nf][2] + p1.x) * SCALE;
            float s11 = (sacc[nf][3] + p1.y) * SCALE;
            sacc[nf][0] = (jc     <= gi0 + 512) ? s00 : -1e30f;
            sacc[nf][1] = (jc + 1 <= gi0 + 512) ? s01 : -1e30f;
            sacc[nf][2] = (jc     <= gi1 + 512) ? s10 : -1e30f;
            sacc[nf][3] = (jc + 1 <= gi1 + 512) ? s11 : -1e30f;
            mnew0 = fmaxf(mnew0, fmaxf(sacc[nf][0], sacc[nf][1]));
            mnew1 = fmaxf(mnew1, fmaxf(sacc[nf][2], sacc[nf][3]));
        }
#pragma unroll
        for (int d = 1; d < 4; d <<= 1) {
            mnew0 = fmaxf(mnew0, __shfl_xor_sync(0xffffffffu, mnew0, d));
            mnew1 = fmaxf(mnew1, __shfl_xor_sync(0xffffffffu, mnew1, d));
        }
        float fs0 = __expf(mrow0 - mnew0);
        float fs1 = __expf(mrow1 - mnew1);
        mrow0 = mnew0; mrow1 = mnew1;
        float ps0 = 0.f, ps1 = 0.f;
#pragma unroll
        for (int nf = 0; nf < 8; ++nf) {
            sacc[nf][0] = __expf(sacc[nf][0] - mnew0);
            sacc[nf][1] = __expf(sacc[nf][1] - mnew0);
            sacc[nf][2] = __expf(sacc[nf][2] - mnew1);
            sacc[nf][3] = __expf(sacc[nf][3] - mnew1);
            ps0 += sacc[nf][0] + sacc[nf][1];
            ps1 += sacc[nf][2] + sacc[nf][3];
        }
#pragma unroll
        for (int d = 1; d < 4; d <<= 1) {
            ps0 += __shfl_xor_sync(0xffffffffu, ps0, d);
            ps1 += __shfl_xor_sync(0xffffffffu, ps1, d);
        }
        lrow0 = lrow0 * fs0 + ps0;
        lrow1 = lrow1 * fs1 + ps1;
#pragma unroll
        for (int nf = 0; nf < 16; ++nf) {
            of[nf][0] *= fs0; of[nf][1] *= fs0;
            of[nf][2] *= fs1; of[nf][3] *= fs1;
        }

        // store P to warp-private sP rows (fp16 pairs, swizzled)
#pragma unroll
        for (int nf = 0; nf < 8; ++nf) {
            int c  = nf * 8 + c0l;
            int ch = c >> 3, wi = (c >> 1) & 3;
            int row0 = w * 16 + r0l;
            sP[row0 * 32 + ((ch ^ (row0 & 7)) << 2) + wi] = f2h2(sacc[nf][0], sacc[nf][1]);
            int row1 = row0 + 8;
            sP[row1 * 32 + ((ch ^ (row1 & 7)) << 2) + wi] = f2h2(sacc[nf][2], sacc[nf][3]);
        }
        __syncwarp();

        // O += P V^T
#pragma unroll
        for (int ks = 0; ks < 4; ++ks) {
            uint32_t pa[4];
            {
                int row = w * 16 + ((lm & 1) << 3) + lrow;
                int ch  = ks * 2 + (lm >> 1);
                ldsm4(pa[0], pa[1], pa[2], pa[3],
                      sPb + ((row * 32 + ((ch ^ lrow) << 2)) << 2));
            }
#pragma unroll
            for (int nb = 0; nb < 8; ++nb) {
                uint32_t bv[4];
                int rowb = nb * 16 + ((lm >> 1) << 3) + lrow;
                int chb  = ks * 2 + (lm & 1);
                ldsm4(bv[0], bv[1], bv[2], bv[3],
                      smb + ((sb + 4096 + rowb * 32 + ((chb ^ lrow) << 2)) << 2));
                mma16(of[nb * 2],     pa, bv[0], bv[1]);
                mma16(of[nb * 2 + 1], pa, bv[2], bv[3]);
            }
        }
        __syncthreads();
    }

    // normalize + write O (fp16)
    float inv0 = 1.f / lrow0, inv1 = 1.f / lrow1;
    int b = bh >> 3, h = bh & 7;
#pragma unroll
    for (int nf = 0; nf < 16; ++nf) {
        int d = nf * 8 + c0l;
        *(uint32_t*)&g_O[(size_t)(gi0 * 16 + b) * 1024 + h * 128 + d] = f2h2(of[nf][0] * inv0, of[nf][1] * inv0);
        *(uint32_t*)&g_O[(size_t)(gi1 * 16 + b) * 1024 + h * 128 + d] = f2h2(of[nf][2] * inv1, of[nf][3] * inv1);
    }
}

__global__ void copy_k(const float* __restrict__ src, float* __restrict__ dst) {
    int idx = blockIdx.x * blockDim.x + threadIdx.x;
    ((float4*)dst)[idx] = ((const float4*)src)[idx];
}

extern "C" void kernel_launch(void* const* d_in, const int* in_sizes, int n_in,
                              void* d_out, int out_size) {
    const float* inputs = (const float*)d_in[0];
    const float* memory = (const float*)d_in[1];
    const float* w_kv   = (const float*)d_in[2];
    const float* w_q    = (const float*)d_in[3];
    const float* w_p    = (const float*)d_in[4];
    const float* w_out  = (const float*)d_in[5];
    const float* u      = (const float*)d_in[6];
    const float* v      = (const float*)d_in[7];
    float* out = (float*)d_out;

    int writeAux = (out_size >= 3 * 1048576) ? 1 : 0;

    // smem: 2 stages x 40KB + sP 8KB = 90112 B
    cudaFuncSetAttribute(flash_k, cudaFuncAttributeMaxDynamicSharedMemorySize, 90112);

    pe_fill<<<256, 256>>>();
    // kv proj: M=16384 (128 m-tiles, MI=8), N=2048
    gemm_k<0, 8><<<dim3(32, 16, 1), 256>>>(inputs, memory, w_kv, nullptr, nullptr, nullptr, 0);
    // q proj: M=8192 (64 m-tiles, MI=8), N=1024
    gemm_k<1, 8><<<dim3(16, 8, 1), 256>>>(inputs, nullptr, w_q, u, v, nullptr, 0);
    // p proj: M=1024 (8 m-tiles, MI=2), N=1024
    gemm_k<2, 2><<<dim3(16, 4, 1), 256>>>(inputs, nullptr, w_p, nullptr, nullptr, nullptr, 0);
    // position scores (shifted epilogue): M=512, N=1024, z=128, MI=1
    gemm_k<4, 1><<<dim3(16, 4, 128), 256>>>(inputs, nullptr, nullptr, nullptr, nullptr, nullptr, 0);
    // fused flash attention: 64-row CTAs, 128 threads, 2 CTAs/SM
    flash_k<<<dim3(8, 128), 128, 90112>>>();
    // out proj: M=8192, N=128, K=1024
    gemm_k<6, 1><<<dim3(2, 64), 256>>>(inputs, nullptr, w_out, nullptr, nullptr, out, writeAux);
    if (writeAux) copy_k<<<1024, 256>>>(inputs, out + 1048576);
}

// round 15
// speedup vs baseline: 1.1655x; 1.1655x over previous
#include <cuda_runtime.h>
#include <cuda_fp16.h>
#include <math.h>
#include <stdint.h>

#define SCALE 0.088388347648318447f            // 1/sqrt(128)
#define SCALE2 0.12753102765879392f            // SCALE * log2(e)

// ---- static scratch (allocation-free), fp16 intermediates ----
__device__ __half g_K  [16777216];   // [b,h,j,d]
__device__ __half g_Vt [16777216];   // [b,h,d,j]
__device__ __half g_QU [8388608];    // [b,h,i,d]  q+u
__device__ __half g_QV [8388608];    // [b,h,i,d]  q+v
__device__ __half g_P  [1048576];    // [h,jj,d]
__device__ __half g_S2 [67108864];   // [bh,i,j]   shifted position scores (valid j<=i+512)
__device__ __half g_O  [8388608];    // [i*B+b, h*128+d]
__device__ float  g_PE [131072];     // [jj,e]

// pe table + (optional) middle-third output copy, fused
__global__ void pe_fill(const float* __restrict__ inputs, float* __restrict__ dout, int writeAux) {
    int idx = blockIdx.x * blockDim.x + threadIdx.x;
    if (idx < 65536) {
        int jj = idx >> 6, e2 = idx & 63;
        double pos  = (double)(1023 - jj);
        double invf = exp(-((double)e2 / 64.0) * log(10000.0));
        double ang  = pos * invf;
        g_PE[jj * 128 + e2]      = (float)sin(ang);
        g_PE[jj * 128 + 64 + e2] = (float)cos(ang);
    }
    if (writeAux) {
        for (int i = idx; i < 262144; i += gridDim.x * blockDim.x)
            ((float4*)(dout + 1048576))[i] = ((const float4*)inputs)[i];
    }
}

__device__ __forceinline__ uint32_t f2h2(float a, float b) {
    __half2 h = __floats2half2_rn(a, b);
    return *reinterpret_cast<uint32_t*>(&h);
}
__device__ __forceinline__ void ldsm4(uint32_t& r0, uint32_t& r1, uint32_t& r2, uint32_t& r3, uint32_t addr) {
    asm volatile("ldmatrix.sync.aligned.m8n8.x4.shared.b16 {%0,%1,%2,%3}, [%4];"
                 : "=r"(r0), "=r"(r1), "=r"(r2), "=r"(r3) : "r"(addr));
}
__device__ __forceinline__ void mma16(float* c, const uint32_t* a, uint32_t b0, uint32_t b1) {
    asm volatile("mma.sync.aligned.m16n8k16.row.col.f32.f16.f16.f32 "
                 "{%0,%1,%2,%3},{%4,%5,%6,%7},{%8,%9},{%0,%1,%2,%3};"
                 : "+f"(c[0]), "+f"(c[1]), "+f"(c[2]), "+f"(c[3])
                 : "r"(a[0]), "r"(a[1]), "r"(a[2]), "r"(a[3]), "r"(b0), "r"(b1));
}
__device__ __forceinline__ void cpa16(uint32_t saddr, const void* gptr) {
    asm volatile("cp.async.cg.shared.global [%0], [%1], 16;" :: "r"(saddr), "l"(gptr));
}
__device__ __forceinline__ void cp_commit() { asm volatile("cp.async.commit_group;"); }
template<int N> __device__ __forceinline__ void cp_wait() { asm volatile("cp.async.wait_group %0;" :: "n"(N)); }

// ---- fp16 tensor-core NT GEMM: C[M,N] = A[M,K] * W[N,K]^T ----
// BM=128, BN=64, BK=64 halves; 8 warps, each 32x32 via m16n8k16.
// Double-buffered smem, ONE barrier per K-iter.
// MODE 0: kv proj  1: q proj  2: p proj  4: pos scores (rel-shift epilogue)  6: out proj
template<int MODE>
__global__ void __launch_bounds__(256, 2) gemm_k(
    const float* __restrict__ inputs, const float* __restrict__ mem0,
    const float* __restrict__ Wext, const float* __restrict__ uu,
    const float* __restrict__ vv, float* __restrict__ dout, int writeAux)
{
    constexpr int K   = (MODE >= 5) ? 1024 : 128;  // elements
    constexpr int KIT = K / 64;
    constexpr bool AF32 = (MODE <= 2);
    constexpr bool BF32 = (MODE <= 2 || MODE == 6);
    const int z  = blockIdx.z;
    const int m0 = blockIdx.y * 128, n0 = blockIdx.x * 64;
    if (MODE == 4 && m0 + n0 + 190 < 511) return;  // fully outside used band
    const int tid = threadIdx.x;
    const int lane = tid & 31, w = tid >> 5;
    const int wm = w >> 1, wn = w & 1;

    const float* Af = nullptr;
    const __half* Ah = nullptr;
    const float* Bf = Wext;
    const __half* Bh = nullptr;
    if (MODE == 1) Af = inputs;
    if (MODE == 2) Af = g_PE;
    if (MODE == 4) { Ah = g_QV + (size_t)z * 65536;  Bh = g_P + (size_t)(z & 7) * 131072; }
    if (MODE == 6) { Ah = g_O; }

    __shared__ uint32_t As[2][4096];
    __shared__ uint32_t Bs[2][2048];
    uint32_t as_addr = (uint32_t)__cvta_generic_to_shared(As);
    uint32_t bs_addr = (uint32_t)__cvta_generic_to_shared(Bs);

    float acc[2][4][4];
#pragma unroll
    for (int a = 0; a < 2; ++a)
#pragma unroll
        for (int b = 0; b < 4; ++b)
#pragma unroll
            for (int c = 0; c < 4; ++c) acc[a][b][c] = 0.f;

    float4 pa32[4][2], pb32[2][2];
    uint4 pa16[4], pb16[2];

    auto loadA = [&](int it) {
#pragma unroll
        for (int i = 0; i < 4; ++i) {
            int idx = tid + i * 256;
            int row = idx >> 3, ch = idx & 7;
            int r = m0 + row;
            if (AF32) {
                const float* Ap;
                if (MODE == 0)
                    Ap = (r < 8192) ? (mem0 + (size_t)r * 128)
                                    : (inputs + (size_t)(r - 8192) * 128);
                else
                    Ap = Af + (size_t)r * K;
                pa32[i][0] = *(const float4*)(Ap + it * 64 + ch * 8);
                pa32[i][1] = *(const float4*)(Ap + it * 64 + ch * 8 + 4);
            } else {
                pa16[i] = *(const uint4*)(Ah + (size_t)r * K + it * 64 + ch * 8);
            }
        }
    };
    auto loadB = [&](int it) {
#pragma unroll
        for (int i = 0; i < 2; ++i) {
            int idx = tid + i * 256;
            int row = idx >> 3, ch = idx & 7;
            if (BF32) {
                pb32[i][0] = *(const float4*)(Bf + (size_t)(n0 + row) * K + it * 64 + ch * 8);
                pb32[i][1] = *(const float4*)(Bf + (size_t)(n0 + row) * K + it * 64 + ch * 8 + 4);
            } else {
                pb16[i] = *(const uint4*)(Bh + (size_t)(n0 + row) * K + it * 64 + ch * 8);
            }
        }
    };
    auto stage = [&](int s) {
#pragma unroll
        for (int i = 0; i < 4; ++i) {
            int idx = tid + i * 256;
            int row = idx >> 3, ch = idx & 7;
            uint32_t off = row * 32 + ((ch ^ (row & 7)) << 2);
            uint4 v;
            if (AF32) v = make_uint4(f2h2(pa32[i][0].x, pa32[i][0].y), f2h2(pa32[i][0].z, pa32[i][0].w),
                                     f2h2(pa32[i][1].x, pa32[i][1].y), f2h2(pa32[i][1].z, pa32[i][1].w));
            else v = pa16[i];
            *(uint4*)&As[s][off] = v;
        }
#pragma unroll
        for (int i = 0; i < 2; ++i) {
            int idx = tid + i * 256;
            int row = idx >> 3, ch = idx & 7;
            uint32_t off = row * 32 + ((ch ^ (row & 7)) << 2);
            uint4 v;
            if (BF32) v = make_uint4(f2h2(pb32[i][0].x, pb32[i][0].y), f2h2(pb32[i][0].z, pb32[i][0].w),
                                     f2h2(pb32[i][1].x, pb32[i][1].y), f2h2(pb32[i][1].z, pb32[i][1].w));
            else v = pb16[i];
            *(uint4*)&Bs[s][off] = v;
        }
    };

    loadA(0); loadB(0);
    stage(0);
    __syncthreads();

    const int lrow = lane & 7, lm = lane >> 3;
    for (int it = 0; it < KIT; ++it) {
        const int s = it & 1;
        if (it + 1 < KIT) { loadA(it + 1); loadB(it + 1); }
#pragma unroll
        for (int ks = 0; ks < 4; ++ks) {  // k16 steps within BK=64
            uint32_t afr[2][4], bfr[2][4];
#pragma unroll
            for (int mi = 0; mi < 2; ++mi) {
                int row = wm * 32 + mi * 16 + ((lm & 1) << 3) + lrow;
                int ch  = ks * 2 + (lm >> 1);
                ldsm4(afr[mi][0], afr[mi][1], afr[mi][2], afr[mi][3],
                      as_addr + ((s * 4096 + row * 32 + ((ch ^ lrow) << 2)) << 2));
            }
#pragma unroll
            for (int np = 0; np < 2; ++np) {
                int row = wn * 32 + np * 16 + ((lm >> 1) << 3) + lrow;
                int ch  = ks * 2 + (lm & 1);
                ldsm4(bfr[np][0], bfr[np][1], bfr[np][2], bfr[np][3],
                      bs_addr + ((s * 2048 + row * 32 + ((ch ^ lrow) << 2)) << 2));
            }
#pragma unroll
            for (int mi = 0; mi < 2; ++mi)
#pragma unroll
                for (int nj = 0; nj < 4; ++nj)
                    mma16(acc[mi][nj], afr[mi], bfr[nj >> 1][(nj & 1) * 2], bfr[nj >> 1][(nj & 1) * 2 + 1]);
        }
        if (it + 1 < KIT) { stage(s ^ 1); __syncthreads(); }
    }

    // ---- epilogue ----
    const int r0l = lane >> 2, c0l = (lane & 3) * 2;
#pragma unroll
    for (int mi = 0; mi < 2; ++mi)
#pragma unroll
        for (int nj = 0; nj < 4; ++nj)
#pragma unroll
            for (int e = 0; e < 4; ++e) {
                int r = m0 + wm * 32 + mi * 16 + r0l + ((e >= 2) ? 8 : 0);
                int n = n0 + wn * 32 + nj * 8 + c0l + (e & 1);
                float val = acc[mi][nj][e];
                if (MODE == 0) {
                    int j = r >> 4, b = r & 15;
                    if (n < 1024) {
                        int h = n >> 7, d = n & 127;
                        g_K[(size_t)((b * 8 + h) * 1024 + j) * 128 + d] = __float2half(val);
                    } else {
                        int n2 = n - 1024; int h = n2 >> 7, d = n2 & 127;
                        g_Vt[(size_t)((b * 8 + h) * 128 + d) * 1024 + j] = __float2half(val);
                    }
                } else if (MODE == 1) {
                    int i = r >> 4, b = r & 15;
                    size_t base = (size_t)((b * 8 + (n >> 7)) * 512 + i) * 128 + (n & 127);
                    g_QU[base] = __float2half(val + uu[n]);
                    g_QV[base] = __float2half(val + vv[n]);
                } else if (MODE == 2) {
                    g_P[(size_t)((n >> 7) * 1024 + r) * 128 + (n & 127)] = __float2half(val);
                } else if (MODE == 4) {
                    int j = n - 511 + r;  // rel-shift: S2shift[i][j] = S2[i][511+j-i]
                    if (j >= 0 && j < 1024)
                        g_S2[(size_t)z * 524288 + (size_t)r * 1024 + j] = __float2half(val);
                } else {  // MODE 6
                    dout[(size_t)r * 128 + n] = val;
                    if (writeAux) dout[2097152 + (size_t)r * 128 + n] = val;
                }
            }
}

// ---- fused flash attention (fp16): 64-row CTAs, 128 threads, 2 CTAs/SM ----
// S = QK^T + S2shift, masked online softmax (log2 domain), O = P V.
// K, V, S2 tiles double-buffered via cp.async: jt+1 loads overlap jt compute.
// Per stage (10240 u32): K at +0 (2 segs x 2048), V at +4096, S2 at +8192 (64 rows).
__global__ void __launch_bounds__(128, 2) flash_k() {
    extern __shared__ uint32_t sm[];
    uint32_t* sP = sm + 20480;     // 64 i-rows x 32 u32
    const uint32_t smb = (uint32_t)__cvta_generic_to_shared(sm);
    const uint32_t sPb = (uint32_t)__cvta_generic_to_shared(sP);

    const int bh = blockIdx.y;
    const int ix = 7 - blockIdx.x;     // heavy tiles launch first
    const int i0 = ix * 64;
    const int tid = threadIdx.x, lane = tid & 31, w = tid >> 5;  // w in 0..3
    const int lrow = lane & 7, lm = lane >> 3;
    const int r0l = lane >> 2, c0l = (lane & 3) * 2;

    const __half* Qb  = g_QU + (size_t)bh * 65536;
    const __half* Kb  = g_K  + (size_t)bh * 131072;
    const __half* Vb  = g_Vt + (size_t)bh * 131072;
    const __half* S2b = g_S2 + (size_t)bh * 524288;

    uint32_t qf[8][4];

    // ---- Q fragments via smem staging (single 64-row pass into stage-0 K region) ----
#pragma unroll
    for (int t = 0; t < 8; ++t) {
        int idx = tid + t * 128;
        int row = idx >> 4, c16 = idx & 15;
        int seg = c16 >> 3, ch = c16 & 7;
        uint4 v = *(const uint4*)(Qb + (size_t)(i0 + row) * 128 + c16 * 8);
        *(uint4*)&sm[seg * 2048 + row * 32 + ((ch ^ (row & 7)) << 2)] = v;
    }
    __syncthreads();
    {
        int wr = w * 16;
#pragma unroll
        for (int ks = 0; ks < 8; ++ks) {
            int row = wr + ((lm & 1) << 3) + lrow;
            int seg = ks >> 2, ch = (ks & 3) * 2 + (lm >> 1);
            ldsm4(qf[ks][0], qf[ks][1], qf[ks][2], qf[ks][3],
                  smb + ((seg * 2048 + row * 32 + ((ch ^ lrow) << 2)) << 2));
        }
    }
    __syncthreads();

    // cp.async prefetch of one jt tile (K 16KB + V 16KB + S2 8KB) into stage s
    auto pref = [&](int jt, int s) {
        int j0 = jt * 64;
        int sb = s * 10240;
#pragma unroll
        for (int t = 0; t < 8; ++t) {
            int idx = tid + t * 128;
            int row = idx >> 4, c16 = idx & 15;
            int seg = c16 >> 3, ch = c16 & 7;
            cpa16(smb + ((sb + seg * 2048 + row * 32 + ((ch ^ (row & 7)) << 2)) << 2),
                  Kb + (size_t)(j0 + row) * 128 + c16 * 8);
        }
#pragma unroll
        for (int t = 0; t < 8; ++t) {
            int idx = tid + t * 128;
            int row = idx >> 3, ch = idx & 7;
            cpa16(smb + ((sb + 4096 + row * 32 + ((ch ^ (row & 7)) << 2)) << 2),
                  Vb + (size_t)row * 1024 + j0 + ch * 8);
        }
#pragma unroll
        for (int t = 0; t < 4; ++t) {
            int idx = tid + t * 128;
            int row = idx >> 3, ch = idx & 7;
            cpa16(smb + ((sb + 8192 + row * 32 + ((ch ^ (row & 7)) << 2)) << 2),
                  S2b + (size_t)(i0 + row) * 1024 + j0 + ch * 8);
        }
    };

    float of[16][4];
#pragma unroll
    for (int a = 0; a < 16; ++a)
#pragma unroll
        for (int e = 0; e < 4; ++e) of[a][e] = 0.f;
    float mrow0 = -1e30f, mrow1 = -1e30f;    // log2-domain running max
    float lrow0 = 0.f, lrow1 = 0.f;

    const int gi0 = i0 + w * 16 + r0l;
    const int gi1 = gi0 + 8;
    const int lr0 = w * 16 + r0l, lr1 = lr0 + 8;  // local rows in sS2/sP (0..63)
    const int njt = ix + 9;       // covers j <= i0+63+512

    pref(0, 0); cp_commit();

    for (int jt = 0; jt < njt; ++jt) {
        const int s = jt & 1;
        int j0 = jt * 64;
        if (jt + 1 < njt) { pref(jt + 1, s ^ 1); cp_commit(); cp_wait<1>(); }
        else cp_wait<0>();
        __syncthreads();
        const int sb = s * 10240;

        // scores: S = Q K^T (16 x 64 per warp)
        float sacc[8][4];
#pragma unroll
        for (int a = 0; a < 8; ++a)
#pragma unroll
            for (int e = 0; e < 4; ++e) sacc[a][e] = 0.f;
#pragma unroll
        for (int ks = 0; ks < 8; ++ks) {
            uint32_t bfr[4][4];
#pragma unroll
            for (int nb = 0; nb < 4; ++nb) {
                int row = nb * 16 + ((lm >> 1) << 3) + lrow;
                int seg = ks >> 2, ch = (ks & 3) * 2 + (lm & 1);
                ldsm4(bfr[nb][0], bfr[nb][1], bfr[nb][2], bfr[nb][3],
                      smb + ((sb + seg * 2048 + row * 32 + ((ch ^ lrow) << 2)) << 2));
            }
#pragma unroll
            for (int nf = 0; nf < 8; ++nf)
                mma16(sacc[nf], qf[ks], bfr[nf >> 1][(nf & 1) * 2], bfr[nf >> 1][(nf & 1) * 2 + 1]);
        }

        // add shifted position scores (smem), mask, scale into log2 domain, online softmax
        float mnew0 = mrow0, mnew1 = mrow1;
#pragma unroll
        for (int nf = 0; nf < 8; ++nf) {
            int jc = j0 + nf * 8 + c0l;
            uint32_t u0 = sm[sb + 8192 + lr0 * 32 + ((nf ^ r0l) << 2) + (lane & 3)];
            uint32_t u1 = sm[sb + 8192 + lr1 * 32 + ((nf ^ r0l) << 2) + (lane & 3)];
            float2 p0 = __half22float2(*reinterpret_cast<__half2*>(&u0));
            float2 p1 = __half22float2(*reinterpret_cast<__half2*>(&u1));
            float s00 = (sacc[nf][0] + p0.x) * SCALE2;
            float s01 = (sacc[nf][1] + p0.y) * SCALE2;
            float s10 = (sacc[nf][2] + p1.x) * SCALE2;
            float s11 = (sacc[nf][3] + p1.y) * SCALE2;
            sacc[nf][0] = (jc     <= gi0 + 512) ? s00 : -1e30f;
            sacc[nf][1] = (jc + 1 <= gi0 + 512) ? s01 : -1e30f;
            sacc[nf][2] = (jc     <= gi1 + 512) ? s10 : -1e30f;
            sacc[nf][3] = (jc + 1 <= gi1 + 512) ? s11 : -1e30f;
            mnew0 = fmaxf(mnew0, fmaxf(sacc[nf][0], sacc[nf][1]));
            mnew1 = fmaxf(mnew1, fmaxf(sacc[nf][2], sacc[nf][3]));
        }
#pragma unroll
        for (int d = 1; d < 4; d <<= 1) {
            mnew0 = fmaxf(mnew0, __shfl_xor_sync(0xffffffffu, mnew0, d));
            mnew1 = fmaxf(mnew1, __shfl_xor_sync(0xffffffffu, mnew1, d));
        }
        float fs0 = exp2f(mrow0 - mnew0);
        float fs1 = exp2f(mrow1 - mnew1);
        mrow0 = mnew0; mrow1 = mnew1;
        float ps0 = 0.f, ps1 = 0.f;
#pragma unroll
        for (int nf = 0; nf < 8; ++nf) {
            sacc[nf][0] = exp2f(sacc[nf][0] - mnew0);
            sacc[nf][1] = exp2f(sacc[nf][1] - mnew0);
            sacc[nf][2] = exp2f(sacc[nf][2] - mnew1);
            sacc[nf][3] = exp2f(sacc[nf][3] - mnew1);
            ps0 += sacc[nf][0] + sacc[nf][1];
            ps1 += sacc[nf][2] + sacc[nf][3];
        }
#pragma unroll
        for (int d = 1; d < 4; d <<= 1) {
            ps0 += __shfl_xor_sync(0xffffffffu, ps0, d);
            ps1 += __shfl_xor_sync(0xffffffffu, ps1, d);
        }
        lrow0 = lrow0 * fs0 + ps0;
        lrow1 = lrow1 * fs1 + ps1;
#pragma unroll
        for (int nf = 0; nf < 16; ++nf) {
            of[nf][0] *= fs0; of[nf][1] *= fs0;
            of[nf][2] *= fs1; of[nf][3] *= fs1;
        }

        // store P to warp-private sP rows (fp16 pairs, swizzled)
#pragma unroll
        for (int nf = 0; nf < 8; ++nf) {
            int c  = nf * 8 + c0l;
            int ch = c >> 3, wi = (c >> 1) & 3;
            int row0 = w * 16 + r0l;
            sP[row0 * 32 + ((ch ^ (row0 & 7)) << 2) + wi] = f2h2(sacc[nf][0], sacc[nf][1]);
            int row1 = row0 + 8;
            sP[row1 * 32 + ((ch ^ (row1 & 7)) << 2) + wi] = f2h2(sacc[nf][2], sacc[nf][3]);
        }
        __syncwarp();

        // O += P V^T
#pragma unroll
        for (int ks = 0; ks < 4; ++ks) {
            uint32_t pa[4];
            {
                int row = w * 16 + ((lm & 1) << 3) + lrow;
                int ch  = ks * 2 + (lm >> 1);
                ldsm4(pa[0], pa[1], pa[2], pa[3],
                      sPb + ((row * 32 + ((ch ^ lrow) << 2)) << 2));
            }
#pragma unroll
            for (int nb = 0; nb < 8; ++nb) {
                uint32_t bv[4];
                int rowb = nb * 16 + ((lm >> 1) << 3) + lrow;
                int chb  = ks * 2 + (lm & 1);
                ldsm4(bv[0], bv[1], bv[2], bv[3],
                      smb + ((sb + 4096 + rowb * 32 + ((chb ^ lrow) << 2)) << 2));
                mma16(of[nb * 2],     pa, bv[0], bv[1]);
                mma16(of[nb * 2 + 1], pa, bv[2], bv[3]);
            }
        }
        __syncthreads();
    }

    // normalize + write O (fp16)
    float inv0 = 1.f / lrow0, inv1 = 1.f / lrow1;
    int b = bh >> 3, h = bh & 7;
#pragma unroll
    for (int nf = 0; nf < 16; ++nf) {
        int d = nf * 8 + c0l;
        *(uint32_t*)&g_O[(size_t)(gi0 * 16 + b) * 1024 + h * 128 + d] = f2h2(of[nf][0] * inv0, of[nf][1] * inv0);
        *(uint32_t*)&g_O[(size_t)(gi1 * 16 + b) * 1024 + h * 128 + d] = f2h2(of[nf][2] * inv1, of[nf][3] * inv1);
    }
}

extern "C" void kernel_launch(void* const* d_in, const int* in_sizes, int n_in,
                              void* d_out, int out_size) {
    const float* inputs = (const float*)d_in[0];
    const float* memory = (const float*)d_in[1];
    const float* w_kv   = (const float*)d_in[2];
    const float* w_q    = (const float*)d_in[3];
    const float* w_p    = (const float*)d_in[4];
    const float* w_out  = (const float*)d_in[5];
    const float* u      = (const float*)d_in[6];
    const float* v      = (const float*)d_in[7];
    float* out = (float*)d_out;

    int writeAux = (out_size >= 3 * 1048576) ? 1 : 0;

    // smem: 2 stages x 40KB + sP 8KB = 90112 B
    cudaFuncSetAttribute(flash_k, cudaFuncAttributeMaxDynamicSharedMemorySize, 90112);

    // pe table + middle-third output copy (fused)
    pe_fill<<<256, 256>>>(inputs, out, writeAux);
    // kv proj: M=16384, N=2048, K=128
    gemm_k<0><<<dim3(32, 128, 1), 256>>>(inputs, memory, w_kv, nullptr, nullptr, nullptr, 0);
    // q proj: M=8192, N=1024, K=128
    gemm_k<1><<<dim3(16, 64, 1), 256>>>(inputs, nullptr, w_q, u, v, nullptr, 0);
    // p proj: M=1024, N=1024, K=128
    gemm_k<2><<<dim3(16, 8, 1), 256>>>(inputs, nullptr, w_p, nullptr, nullptr, nullptr, 0);
    // position scores (shifted epilogue): M=512, N=1024, K=128, z=128
    gemm_k<4><<<dim3(16, 4, 128), 256>>>(inputs, nullptr, nullptr, nullptr, nullptr, nullptr, 0);
    // fused flash attention: 64-row CTAs, 128 threads, 2 CTAs/SM
    flash_k<<<dim3(8, 128), 128, 90112>>>();
    // out proj: M=8192, N=128, K=1024
    gemm_k<6><<<dim3(2, 64), 256>>>(inputs, nullptr, w_out, nullptr, nullptr, out, writeAux);
}

// round 16
// speedup vs baseline: 1.1866x; 1.0181x over previous
#include <cuda_runtime.h>
#include <cuda_fp16.h>
#include <math.h>
#include <stdint.h>

#define SCALE 0.088388347648318447f            // 1/sqrt(128)
#define SCALE2 0.12753102765879392f            // SCALE * log2(e)

// ---- static scratch (allocation-free), fp16 intermediates ----
__device__ __half g_K  [16777216];   // [b,h,j,d]
__device__ __half g_Vt [16777216];   // [b,h,d,j]
__device__ __half g_QU [8388608];    // [b,h,i,d]  q+u
__device__ __half g_QV [8388608];    // [b,h,i,d]  q+v
__device__ __half g_P  [1048576];    // [h,jj,d]
__device__ __half g_S2 [67108864];   // [bh,i,j]   shifted position scores (valid j<=i+512)
__device__ __half g_O  [8388608];    // [i*B+b, h*128+d]
__device__ float  g_PE [131072];     // [jj,e]

// pe table + (optional) middle-third output copy, fused
__global__ void pe_fill(const float* __restrict__ inputs, float* __restrict__ dout, int writeAux) {
    int idx = blockIdx.x * blockDim.x + threadIdx.x;
    if (idx < 65536) {
        int jj = idx >> 6, e2 = idx & 63;
        double pos  = (double)(1023 - jj);
        double invf = exp(-((double)e2 / 64.0) * log(10000.0));
        double ang  = pos * invf;
        g_PE[jj * 128 + e2]      = (float)sin(ang);
        g_PE[jj * 128 + 64 + e2] = (float)cos(ang);
    }
    if (writeAux) {
        for (int i = idx; i < 262144; i += gridDim.x * blockDim.x)
            ((float4*)(dout + 1048576))[i] = ((const float4*)inputs)[i];
    }
}

__device__ __forceinline__ uint32_t f2h2(float a, float b) {
    __half2 h = __floats2half2_rn(a, b);
    return *reinterpret_cast<uint32_t*>(&h);
}
__device__ __forceinline__ void ldsm4(uint32_t& r0, uint32_t& r1, uint32_t& r2, uint32_t& r3, uint32_t addr) {
    asm volatile("ldmatrix.sync.aligned.m8n8.x4.shared.b16 {%0,%1,%2,%3}, [%4];"
                 : "=r"(r0), "=r"(r1), "=r"(r2), "=r"(r3) : "r"(addr));
}
__device__ __forceinline__ void mma16(float* c, const uint32_t* a, uint32_t b0, uint32_t b1) {
    asm volatile("mma.sync.aligned.m16n8k16.row.col.f32.f16.f16.f32 "
                 "{%0,%1,%2,%3},{%4,%5,%6,%7},{%8,%9},{%0,%1,%2,%3};"
                 : "+f"(c[0]), "+f"(c[1]), "+f"(c[2]), "+f"(c[3])
                 : "r"(a[0]), "r"(a[1]), "r"(a[2]), "r"(a[3]), "r"(b0), "r"(b1));
}
__device__ __forceinline__ void cpa16(uint32_t saddr, const void* gptr) {
    asm volatile("cp.async.cg.shared.global [%0], [%1], 16;" :: "r"(saddr), "l"(gptr));
}
__device__ __forceinline__ void cp_commit() { asm volatile("cp.async.commit_group;"); }
template<int N> __device__ __forceinline__ void cp_wait() { asm volatile("cp.async.wait_group %0;" :: "n"(N)); }

// ---- fp16 tensor-core NT GEMM: C[M,N] = A[M,K] * W[N,K]^T ----
// BM=128, BN=64, BK=64 halves; 8 warps, each 32x32 via m16n8k16.
// Double-buffered smem, ONE barrier per K-iter.
// MODE 0: kv proj  1: q proj  2: p proj  4: pos scores (rel-shift epilogue)  6: out proj
template<int MODE>
__global__ void __launch_bounds__(256, 2) gemm_k(
    const float* __restrict__ inputs, const float* __restrict__ mem0,
    const float* __restrict__ Wext, const float* __restrict__ uu,
    const float* __restrict__ vv, float* __restrict__ dout, int writeAux)
{
    constexpr int K   = (MODE >= 5) ? 1024 : 128;  // elements
    constexpr int KIT = K / 64;
    constexpr bool AF32 = (MODE <= 2);
    constexpr bool BF32 = (MODE <= 2 || MODE == 6);
    const int z  = blockIdx.z;
    const int m0 = blockIdx.y * 128, n0 = blockIdx.x * 64;
    if (MODE == 4 && m0 + n0 + 190 < 511) return;  // fully outside used band
    const int tid = threadIdx.x;
    const int lane = tid & 31, w = tid >> 5;
    const int wm = w >> 1, wn = w & 1;

    const float* Af = nullptr;
    const __half* Ah = nullptr;
    const float* Bf = Wext;
    const __half* Bh = nullptr;
    if (MODE == 1) Af = inputs;
    if (MODE == 2) Af = g_PE;
    if (MODE == 4) { Ah = g_QV + (size_t)z * 65536;  Bh = g_P + (size_t)(z & 7) * 131072; }
    if (MODE == 6) { Ah = g_O; }

    __shared__ uint32_t As[2][4096];
    __shared__ uint32_t Bs[2][2048];
    uint32_t as_addr = (uint32_t)__cvta_generic_to_shared(As);
    uint32_t bs_addr = (uint32_t)__cvta_generic_to_shared(Bs);

    float acc[2][4][4];
#pragma unroll
    for (int a = 0; a < 2; ++a)
#pragma unroll
        for (int b = 0; b < 4; ++b)
#pragma unroll
            for (int c = 0; c < 4; ++c) acc[a][b][c] = 0.f;

    float4 pa32[4][2], pb32[2][2];
    uint4 pa16[4], pb16[2];

    auto loadA = [&](int it) {
#pragma unroll
        for (int i = 0; i < 4; ++i) {
            int idx = tid + i * 256;
            int row = idx >> 3, ch = idx & 7;
            int r = m0 + row;
            if (AF32) {
                const float* Ap;
                if (MODE == 0)
                    Ap = (r < 8192) ? (mem0 + (size_t)r * 128)
                                    : (inputs + (size_t)(r - 8192) * 128);
                else
                    Ap = Af + (size_t)r * K;
                pa32[i][0] = *(const float4*)(Ap + it * 64 + ch * 8);
                pa32[i][1] = *(const float4*)(Ap + it * 64 + ch * 8 + 4);
            } else {
                pa16[i] = *(const uint4*)(Ah + (size_t)r * K + it * 64 + ch * 8);
            }
        }
    };
    auto loadB = [&](int it) {
#pragma unroll
        for (int i = 0; i < 2; ++i) {
            int idx = tid + i * 256;
            int row = idx >> 3, ch = idx & 7;
            if (BF32) {
                pb32[i][0] = *(const float4*)(Bf + (size_t)(n0 + row) * K + it * 64 + ch * 8);
                pb32[i][1] = *(const float4*)(Bf + (size_t)(n0 + row) * K + it * 64 + ch * 8 + 4);
            } else {
                pb16[i] = *(const uint4*)(Bh + (size_t)(n0 + row) * K + it * 64 + ch * 8);
            }
        }
    };
    auto stage = [&](int s) {
#pragma unroll
        for (int i = 0; i < 4; ++i) {
            int idx = tid + i * 256;
            int row = idx >> 3, ch = idx & 7;
            uint32_t off = row * 32 + ((ch ^ (row & 7)) << 2);
            uint4 v;
            if (AF32) v = make_uint4(f2h2(pa32[i][0].x, pa32[i][0].y), f2h2(pa32[i][0].z, pa32[i][0].w),
                                     f2h2(pa32[i][1].x, pa32[i][1].y), f2h2(pa32[i][1].z, pa32[i][1].w));
            else v = pa16[i];
            *(uint4*)&As[s][off] = v;
        }
#pragma unroll
        for (int i = 0; i < 2; ++i) {
            int idx = tid + i * 256;
            int row = idx >> 3, ch = idx & 7;
            uint32_t off = row * 32 + ((ch ^ (row & 7)) << 2);
            uint4 v;
            if (BF32) v = make_uint4(f2h2(pb32[i][0].x, pb32[i][0].y), f2h2(pb32[i][0].z, pb32[i][0].w),
                                     f2h2(pb32[i][1].x, pb32[i][1].y), f2h2(pb32[i][1].z, pb32[i][1].w));
            else v = pb16[i];
            *(uint4*)&Bs[s][off] = v;
        }
    };

    loadA(0); loadB(0);
    stage(0);
    __syncthreads();

    const int lrow = lane & 7, lm = lane >> 3;
    for (int it = 0; it < KIT; ++it) {
        const int s = it & 1;
        if (it + 1 < KIT) { loadA(it + 1); loadB(it + 1); }
#pragma unroll
        for (int ks = 0; ks < 4; ++ks) {  // k16 steps within BK=64
            uint32_t afr[2][4], bfr[2][4];
#pragma unroll
            for (int mi = 0; mi < 2; ++mi) {
                int row = wm * 32 + mi * 16 + ((lm & 1) << 3) + lrow;
                int ch  = ks * 2 + (lm >> 1);
                ldsm4(afr[mi][0], afr[mi][1], afr[mi][2], afr[mi][3],
                      as_addr + ((s * 4096 + row * 32 + ((ch ^ lrow) << 2)) << 2));
            }
#pragma unroll
            for (int np = 0; np < 2; ++np) {
                int row = wn * 32 + np * 16 + ((lm >> 1) << 3) + lrow;
                int ch  = ks * 2 + (lm & 1);
                ldsm4(bfr[np][0], bfr[np][1], bfr[np][2], bfr[np][3],
                      bs_addr + ((s * 2048 + row * 32 + ((ch ^ lrow) << 2)) << 2));
            }
#pragma unroll
            for (int mi = 0; mi < 2; ++mi)
#pragma unroll
                for (int nj = 0; nj < 4; ++nj)
                    mma16(acc[mi][nj], afr[mi], bfr[nj >> 1][(nj & 1) * 2], bfr[nj >> 1][(nj & 1) * 2 + 1]);
        }
        if (it + 1 < KIT) { stage(s ^ 1); __syncthreads(); }
    }

    // ---- epilogue ----
    const int r0l = lane >> 2, c0l = (lane & 3) * 2;
#pragma unroll
    for (int mi = 0; mi < 2; ++mi)
#pragma unroll
        for (int nj = 0; nj < 4; ++nj)
#pragma unroll
            for (int e = 0; e < 4; ++e) {
                int r = m0 + wm * 32 + mi * 16 + r0l + ((e >= 2) ? 8 : 0);
                int n = n0 + wn * 32 + nj * 8 + c0l + (e & 1);
                float val = acc[mi][nj][e];
                if (MODE == 0) {
                    int j = r >> 4, b = r & 15;
                    if (n < 1024) {
                        int h = n >> 7, d = n & 127;
                        g_K[(size_t)((b * 8 + h) * 1024 + j) * 128 + d] = __float2half(val);
                    } else {
                        int n2 = n - 1024; int h = n2 >> 7, d = n2 & 127;
                        g_Vt[(size_t)((b * 8 + h) * 128 + d) * 1024 + j] = __float2half(val);
                    }
                } else if (MODE == 1) {
                    int i = r >> 4, b = r & 15;
                    size_t base = (size_t)((b * 8 + (n >> 7)) * 512 + i) * 128 + (n & 127);
                    g_QU[base] = __float2half(val + uu[n]);
                    g_QV[base] = __float2half(val + vv[n]);
                } else if (MODE == 2) {
                    g_P[(size_t)((n >> 7) * 1024 + r) * 128 + (n & 127)] = __float2half(val);
                } else if (MODE == 4) {
                    int j = n - 511 + r;  // rel-shift: S2shift[i][j] = S2[i][511+j-i]
                    if (j >= 0 && j < 1024)
                        g_S2[(size_t)z * 524288 + (size_t)r * 1024 + j] = __float2half(val);
                } else {  // MODE 6
                    dout[(size_t)r * 128 + n] = val;
                    if (writeAux) dout[2097152 + (size_t)r * 128 + n] = val;
                }
            }
}

// ---- fused flash attention (fp16): 64-row CTAs, 128 threads, 2 CTAs/SM ----
// S = QK^T + S2shift, masked online softmax (log2 domain), O = P V.
// P passes from score C-fragments directly into PV A-fragments (layout identity) —
// no smem round-trip. K, V, S2 double-buffered via cp.async.
// Per stage (10240 u32): K at +0 (2 segs x 2048), V at +4096, S2 at +8192 (64 rows).
__global__ void __launch_bounds__(128, 2) flash_k() {
    extern __shared__ uint32_t sm[];
    const uint32_t smb = (uint32_t)__cvta_generic_to_shared(sm);

    const int bh = blockIdx.y;
    const int ix = 7 - blockIdx.x;     // heavy tiles launch first
    const int i0 = ix * 64;
    const int tid = threadIdx.x, lane = tid & 31, w = tid >> 5;  // w in 0..3
    const int lrow = lane & 7, lm = lane >> 3;
    const int r0l = lane >> 2, c0l = (lane & 3) * 2;

    const __half* Qb  = g_QU + (size_t)bh * 65536;
    const __half* Kb  = g_K  + (size_t)bh * 131072;
    const __half* Vb  = g_Vt + (size_t)bh * 131072;
    const __half* S2b = g_S2 + (size_t)bh * 524288;

    uint32_t qf[8][4];

    // ---- Q fragments via smem staging (single 64-row pass into stage-0 K region) ----
#pragma unroll
    for (int t = 0; t < 8; ++t) {
        int idx = tid + t * 128;
        int row = idx >> 4, c16 = idx & 15;
        int seg = c16 >> 3, ch = c16 & 7;
        uint4 v = *(const uint4*)(Qb + (size_t)(i0 + row) * 128 + c16 * 8);
        *(uint4*)&sm[seg * 2048 + row * 32 + ((ch ^ (row & 7)) << 2)] = v;
    }
    __syncthreads();
    {
        int wr = w * 16;
#pragma unroll
        for (int ks = 0; ks < 8; ++ks) {
            int row = wr + ((lm & 1) << 3) + lrow;
            int seg = ks >> 2, ch = (ks & 3) * 2 + (lm >> 1);
            ldsm4(qf[ks][0], qf[ks][1], qf[ks][2], qf[ks][3],
                  smb + ((seg * 2048 + row * 32 + ((ch ^ lrow) << 2)) << 2));
        }
    }
    __syncthreads();

    // cp.async prefetch of one jt tile (K 16KB + V 16KB + S2 8KB) into stage s
    auto pref = [&](int jt, int s) {
        int j0 = jt * 64;
        int sb = s * 10240;
#pragma unroll
        for (int t = 0; t < 8; ++t) {
            int idx = tid + t * 128;
            int row = idx >> 4, c16 = idx & 15;
            int seg = c16 >> 3, ch = c16 & 7;
            cpa16(smb + ((sb + seg * 2048 + row * 32 + ((ch ^ (row & 7)) << 2)) << 2),
                  Kb + (size_t)(j0 + row) * 128 + c16 * 8);
        }
#pragma unroll
        for (int t = 0; t < 8; ++t) {
            int idx = tid + t * 128;
            int row = idx >> 3, ch = idx & 7;
            cpa16(smb + ((sb + 4096 + row * 32 + ((ch ^ (row & 7)) << 2)) << 2),
                  Vb + (size_t)row * 1024 + j0 + ch * 8);
        }
#pragma unroll
        for (int t = 0; t < 4; ++t) {
            int idx = tid + t * 128;
            int row = idx >> 3, ch = idx & 7;
            cpa16(smb + ((sb + 8192 + row * 32 + ((ch ^ (row & 7)) << 2)) << 2),
                  S2b + (size_t)(i0 + row) * 1024 + j0 + ch * 8);
        }
    };

    float of[16][4];
#pragma unroll
    for (int a = 0; a < 16; ++a)
#pragma unroll
        for (int e = 0; e < 4; ++e) of[a][e] = 0.f;
    float mrow0 = -1e30f, mrow1 = -1e30f;    // log2-domain running max
    float lrow0 = 0.f, lrow1 = 0.f;

    const int gi0 = i0 + w * 16 + r0l;
    const int gi1 = gi0 + 8;
    const int lr0 = w * 16 + r0l, lr1 = lr0 + 8;  // local rows in sS2 (0..63)
    const int njt = ix + 9;       // covers j <= i0+63+512

    pref(0, 0); cp_commit();

    for (int jt = 0; jt < njt; ++jt) {
        const int s = jt & 1;
        int j0 = jt * 64;
        if (jt + 1 < njt) { pref(jt + 1, s ^ 1); cp_commit(); cp_wait<1>(); }
        else cp_wait<0>();
        __syncthreads();
        const int sb = s * 10240;

        // scores: S = Q K^T (16 x 64 per warp)
        float sacc[8][4];
#pragma unroll
        for (int a = 0; a < 8; ++a)
#pragma unroll
            for (int e = 0; e < 4; ++e) sacc[a][e] = 0.f;
#pragma unroll
        for (int ks = 0; ks < 8; ++ks) {
            uint32_t bfr[4][4];
#pragma unroll
            for (int nb = 0; nb < 4; ++nb) {
                int row = nb * 16 + ((lm >> 1) << 3) + lrow;
                int seg = ks >> 2, ch = (ks & 3) * 2 + (lm & 1);
                ldsm4(bfr[nb][0], bfr[nb][1], bfr[nb][2], bfr[nb][3],
                      smb + ((sb + seg * 2048 + row * 32 + ((ch ^ lrow) << 2)) << 2));
            }
#pragma unroll
            for (int nf = 0; nf < 8; ++nf)
                mma16(sacc[nf], qf[ks], bfr[nf >> 1][(nf & 1) * 2], bfr[nf >> 1][(nf & 1) * 2 + 1]);
        }

        // add shifted position scores (smem), mask, scale into log2 domain, online softmax
        float mnew0 = mrow0, mnew1 = mrow1;
#pragma unroll
        for (int nf = 0; nf < 8; ++nf) {
            int jc = j0 + nf * 8 + c0l;
            uint32_t u0 = sm[sb + 8192 + lr0 * 32 + ((nf ^ r0l) << 2) + (lane & 3)];
            uint32_t u1 = sm[sb + 8192 + lr1 * 32 + ((nf ^ r0l) << 2) + (lane & 3)];
            float2 p0 = __half22float2(*reinterpret_cast<__half2*>(&u0));
            float2 p1 = __half22float2(*reinterpret_cast<__half2*>(&u1));
            float s00 = (sacc[nf][0] + p0.x) * SCALE2;
            float s01 = (sacc[nf][1] + p0.y) * SCALE2;
            float s10 = (sacc[nf][2] + p1.x) * SCALE2;
            float s11 = (sacc[nf][3] + p1.y) * SCALE2;
            sacc[nf][0] = (jc     <= gi0 + 512) ? s00 : -1e30f;
            sacc[nf][1] = (jc + 1 <= gi0 + 512) ? s01 : -1e30f;
            sacc[nf][2] = (jc     <= gi1 + 512) ? s10 : -1e30f;
            sacc[nf][3] = (jc + 1 <= gi1 + 512) ? s11 : -1e30f;
            mnew0 = fmaxf(mnew0, fmaxf(sacc[nf][0], sacc[nf][1]));
            mnew1 = fmaxf(mnew1, fmaxf(sacc[nf][2], sacc[nf][3]));
        }
#pragma unroll
        for (int d = 1; d < 4; d <<= 1) {
            mnew0 = fmaxf(mnew0, __shfl_xor_sync(0xffffffffu, mnew0, d));
            mnew1 = fmaxf(mnew1, __shfl_xor_sync(0xffffffffu, mnew1, d));
        }
        float fs0 = exp2f(mrow0 - mnew0);
        float fs1 = exp2f(mrow1 - mnew1);
        mrow0 = mnew0; mrow1 = mnew1;
        float ps0 = 0.f, ps1 = 0.f;
#pragma unroll
        for (int nf = 0; nf < 8; ++nf) {
            sacc[nf][0] = exp2f(sacc[nf][0] - mnew0);
            sacc[nf][1] = exp2f(sacc[nf][1] - mnew0);
            sacc[nf][2] = exp2f(sacc[nf][2] - mnew1);
            sacc[nf][3] = exp2f(sacc[nf][3] - mnew1);
            ps0 += sacc[nf][0] + sacc[nf][1];
            ps1 += sacc[nf][2] + sacc[nf][3];
        }
#pragma unroll
        for (int d = 1; d < 4; d <<= 1) {
            ps0 += __shfl_xor_sync(0xffffffffu, ps0, d);
            ps1 += __shfl_xor_sync(0xffffffffu, ps1, d);
        }
        lrow0 = lrow0 * fs0 + ps0;
        lrow1 = lrow1 * fs1 + ps1;
#pragma unroll
        for (int nf = 0; nf < 16; ++nf) {
            of[nf][0] *= fs0; of[nf][1] *= fs0;
            of[nf][2] *= fs1; of[nf][3] *= fs1;
        }

        // O += P V^T — P A-fragments built directly from score C-fragments
        // (m16n8k16 layout identity: A = {h2(c[2ks][0,1]), h2(c[2ks][2,3]),
        //  h2(c[2ks+1][0,1]), h2(c[2ks+1][2,3])}), no smem round-trip.
#pragma unroll
        for (int ks = 0; ks < 4; ++ks) {
            uint32_t pa[4];
            pa[0] = f2h2(sacc[2 * ks][0],     sacc[2 * ks][1]);
            pa[1] = f2h2(sacc[2 * ks][2],     sacc[2 * ks][3]);
            pa[2] = f2h2(sacc[2 * ks + 1][0], sacc[2 * ks + 1][1]);
            pa[3] = f2h2(sacc[2 * ks + 1][2], sacc[2 * ks + 1][3]);
#pragma unroll
            for (int nb = 0; nb < 8; ++nb) {
                uint32_t bv[4];
                int rowb = nb * 16 + ((lm >> 1) << 3) + lrow;
                int chb  = ks * 2 + (lm & 1);
                ldsm4(bv[0], bv[1], bv[2], bv[3],
                      smb + ((sb + 4096 + rowb * 32 + ((chb ^ lrow) << 2)) << 2));
                mma16(of[nb * 2],     pa, bv[0], bv[1]);
                mma16(of[nb * 2 + 1], pa, bv[2], bv[3]);
            }
        }
        __syncthreads();
    }

    // normalize + write O (fp16)
    float inv0 = 1.f / lrow0, inv1 = 1.f / lrow1;
    int b = bh >> 3, h = bh & 7;
#pragma unroll
    for (int nf = 0; nf < 16; ++nf) {
        int d = nf * 8 + c0l;
        *(uint32_t*)&g_O[(size_t)(gi0 * 16 + b) * 1024 + h * 128 + d] = f2h2(of[nf][0] * inv0, of[nf][1] * inv0);
        *(uint32_t*)&g_O[(size_t)(gi1 * 16 + b) * 1024 + h * 128 + d] = f2h2(of[nf][2] * inv1, of[nf][3] * inv1);
    }
}

extern "C" void kernel_launch(void* const* d_in, const int* in_sizes, int n_in,
                              void* d_out, int out_size) {
    const float* inputs = (const float*)d_in[0];
    const float* memory = (const float*)d_in[1];
    const float* w_kv   = (const float*)d_in[2];
    const float* w_q    = (const float*)d_in[3];
    const float* w_p    = (const float*)d_in[4];
    const float* w_out  = (const float*)d_in[5];
    const float* u      = (const float*)d_in[6];
    const float* v      = (const float*)d_in[7];
    float* out = (float*)d_out;

    int writeAux = (out_size >= 3 * 1048576) ? 1 : 0;

    // smem: 2 stages x 40KB = 81920 B
    cudaFuncSetAttribute(flash_k, cudaFuncAttributeMaxDynamicSharedMemorySize, 81920);

    // pe table + middle-third output copy (fused)
    pe_fill<<<256, 256>>>(inputs, out, writeAux);
    // kv proj: M=16384, N=2048, K=128
    gemm_k<0><<<dim3(32, 128, 1), 256>>>(inputs, memory, w_kv, nullptr, nullptr, nullptr, 0);
    // q proj: M=8192, N=1024, K=128
    gemm_k<1><<<dim3(16, 64, 1), 256>>>(inputs, nullptr, w_q, u, v, nullptr, 0);
    // p proj: M=1024, N=1024, K=128
    gemm_k<2><<<dim3(16, 8, 1), 256>>>(inputs, nullptr, w_p, nullptr, nullptr, nullptr, 0);
    // position scores (shifted epilogue): M=512, N=1024, K=128, z=128
    gemm_k<4><<<dim3(16, 4, 128), 256>>>(inputs, nullptr, nullptr, nullptr, nullptr, nullptr, 0);
    // fused flash attention: 64-row CTAs, 128 threads, 2 CTAs/SM
    flash_k<<<dim3(8, 128), 128, 81920>>>();
    // out proj: M=8192, N=128, K=1024
    gemm_k<6><<<dim3(2, 64), 256>>>(inputs, nullptr, w_out, nullptr, nullptr, out, writeAux);
}

// round 17
// speedup vs baseline: 1.2152x; 1.0241x over previous
#include <cuda_runtime.h>
#include <cuda_fp16.h>
#include <math.h>
#include <stdint.h>

#define SCALE 0.088388347648318447f            // 1/sqrt(128)
#define SCALE2 0.12753102765879392f            // SCALE * log2(e)

// ---- static scratch (allocation-free), fp16 intermediates ----
__device__ __half g_A16 [2097152];   // [memory layer0 rows 0..8191 | inputs rows 8192..16383] x 128
__device__ __half g_Wkv [262144];
__device__ __half g_Wq  [131072];
__device__ __half g_Wp  [131072];
__device__ __half g_Wout[131072];
__device__ __half g_PE16[131072];    // [jj,e]
__device__ __half g_K   [16777216];  // [b,h,j,d]
__device__ __half g_Vt  [16777216];  // [b,h,d,j]
__device__ __half g_QU  [8388608];   // [b,h,i,d]  q+u
__device__ __half g_QV  [8388608];   // [b,h,i,d]  q+v
__device__ __half g_P   [1048576];   // [h,jj,d]
__device__ __half g_S2  [67108864];  // [bh,i,j]   shifted position scores (valid j<=i+512)
__device__ __half g_O   [8388608];   // [i*B+b, h*128+d]

__device__ __forceinline__ uint32_t f2h2(float a, float b) {
    __half2 h = __floats2half2_rn(a, b);
    return *reinterpret_cast<uint32_t*>(&h);
}

// prep: PE table (fp16) + fp32->fp16 conversion of all GEMM operands + aux output copy
__global__ void prep_k(
    const float* __restrict__ inputs, const float* __restrict__ memory,
    const float* __restrict__ w_kv, const float* __restrict__ w_q,
    const float* __restrict__ w_p, const float* __restrict__ w_out,
    float* __restrict__ dout, int writeAux)
{
    int idx = blockIdx.x * blockDim.x + threadIdx.x;
    int stride = gridDim.x * blockDim.x;
    if (idx < 65536) {
        int jj = idx >> 6, e2 = idx & 63;
        double pos  = (double)(1023 - jj);
        double invf = exp(-((double)e2 / 64.0) * log(10000.0));
        double ang  = pos * invf;
        g_PE16[jj * 128 + e2]      = __float2half((float)sin(ang));
        g_PE16[jj * 128 + 64 + e2] = __float2half((float)cos(ang));
    }
    // conversions: 8 halves per item over concatenated space of 2752512 halves
    for (int i = idx; i < 344064; i += stride) {
        int h = i * 8;
        const float* src; __half* dst;
        if (h < 2097152)      { src = (h < 1048576) ? (memory + h) : (inputs + h - 1048576); dst = g_A16 + h; }
        else if (h < 2359296) { src = w_kv  + h - 2097152; dst = g_Wkv  + h - 2097152; }
        else if (h < 2490368) { src = w_q   + h - 2359296; dst = g_Wq   + h - 2359296; }
        else if (h < 2621440) { src = w_p   + h - 2490368; dst = g_Wp   + h - 2490368; }
        else                  { src = w_out + h - 2621440; dst = g_Wout + h - 2621440; }
        float4 a = *(const float4*)src;
        float4 b = *(const float4*)(src + 4);
        *(uint4*)dst = make_uint4(f2h2(a.x, a.y), f2h2(a.z, a.w), f2h2(b.x, b.y), f2h2(b.z, b.w));
    }
    if (writeAux) {
        for (int i = idx; i < 262144; i += stride)
            ((float4*)(dout + 1048576))[i] = ((const float4*)inputs)[i];
    }
}

__device__ __forceinline__ void ldsm4(uint32_t& r0, uint32_t& r1, uint32_t& r2, uint32_t& r3, uint32_t addr) {
    asm volatile("ldmatrix.sync.aligned.m8n8.x4.shared.b16 {%0,%1,%2,%3}, [%4];"
                 : "=r"(r0), "=r"(r1), "=r"(r2), "=r"(r3) : "r"(addr));
}
__device__ __forceinline__ void mma16(float* c, const uint32_t* a, uint32_t b0, uint32_t b1) {
    asm volatile("mma.sync.aligned.m16n8k16.row.col.f32.f16.f16.f32 "
                 "{%0,%1,%2,%3},{%4,%5,%6,%7},{%8,%9},{%0,%1,%2,%3};"
                 : "+f"(c[0]), "+f"(c[1]), "+f"(c[2]), "+f"(c[3])
                 : "r"(a[0]), "r"(a[1]), "r"(a[2]), "r"(a[3]), "r"(b0), "r"(b1));
}
__device__ __forceinline__ void cpa16(uint32_t saddr, const void* gptr) {
    asm volatile("cp.async.cg.shared.global [%0], [%1], 16;" :: "r"(saddr), "l"(gptr));
}
__device__ __forceinline__ void cp_commit() { asm volatile("cp.async.commit_group;"); }
template<int N> __device__ __forceinline__ void cp_wait() { asm volatile("cp.async.wait_group %0;" :: "n"(N)); }

// ---- fp16 tensor-core NT GEMM: C[M,N] = A[M,K] * W[N,K]^T ----
// BM=128, BN=64, BK=64 halves; 8 warps, each 32x32 via m16n8k16.
// All operands fp16 in global (one-time prep). Double-buffered smem, ONE barrier per K-iter.
// MODE 0: kv proj  1: q proj  2: p proj  4: pos scores (rel-shift epilogue)  6: out proj
template<int MODE>
__global__ void __launch_bounds__(256, 2) gemm_k(
    const float* __restrict__ uu, const float* __restrict__ vv,
    float* __restrict__ dout, int writeAux)
{
    constexpr int K   = (MODE >= 5) ? 1024 : 128;  // elements
    constexpr int KIT = K / 64;
    const int z  = blockIdx.z;
    const int m0 = blockIdx.y * 128, n0 = blockIdx.x * 64;
    if (MODE == 4 && m0 + n0 + 190 < 511) return;  // fully outside used band
    const int tid = threadIdx.x;
    const int lane = tid & 31, w = tid >> 5;
    const int wm = w >> 1, wn = w & 1;

    const __half* Ah;
    const __half* Bh;
    if (MODE == 0)      { Ah = g_A16;                    Bh = g_Wkv; }
    else if (MODE == 1) { Ah = g_A16 + 1048576;          Bh = g_Wq; }
    else if (MODE == 2) { Ah = g_PE16;                   Bh = g_Wp; }
    else if (MODE == 4) { Ah = g_QV + (size_t)z * 65536; Bh = g_P + (size_t)(z & 7) * 131072; }
    else                { Ah = g_O;                      Bh = g_Wout; }

    __shared__ uint32_t As[2][4096];
    __shared__ uint32_t Bs[2][2048];
    uint32_t as_addr = (uint32_t)__cvta_generic_to_shared(As);
    uint32_t bs_addr = (uint32_t)__cvta_generic_to_shared(Bs);

    float acc[2][4][4];
#pragma unroll
    for (int a = 0; a < 2; ++a)
#pragma unroll
        for (int b = 0; b < 4; ++b)
#pragma unroll
            for (int c = 0; c < 4; ++c) acc[a][b][c] = 0.f;

    uint4 pa16[4], pb16[2];

    auto loadA = [&](int it) {
#pragma unroll
        for (int i = 0; i < 4; ++i) {
            int idx = tid + i * 256;
            int row = idx >> 3, ch = idx & 7;
            pa16[i] = *(const uint4*)(Ah + (size_t)(m0 + row) * K + it * 64 + ch * 8);
        }
    };
    auto loadB = [&](int it) {
#pragma unroll
        for (int i = 0; i < 2; ++i) {
            int idx = tid + i * 256;
            int row = idx >> 3, ch = idx & 7;
            pb16[i] = *(const uint4*)(Bh + (size_t)(n0 + row) * K + it * 64 + ch * 8);
        }
    };
    auto stage = [&](int s) {
#pragma unroll
        for (int i = 0; i < 4; ++i) {
            int idx = tid + i * 256;
            int row = idx >> 3, ch = idx & 7;
            *(uint4*)&As[s][row * 32 + ((ch ^ (row & 7)) << 2)] = pa16[i];
        }
#pragma unroll
        for (int i = 0; i < 2; ++i) {
            int idx = tid + i * 256;
            int row = idx >> 3, ch = idx & 7;
            *(uint4*)&Bs[s][row * 32 + ((ch ^ (row & 7)) << 2)] = pb16[i];
        }
    };

    loadA(0); loadB(0);
    stage(0);
    __syncthreads();

    const int lrow = lane & 7, lm = lane >> 3;
    for (int it = 0; it < KIT; ++it) {
        const int s = it & 1;
        if (it + 1 < KIT) { loadA(it + 1); loadB(it + 1); }
#pragma unroll
        for (int ks = 0; ks < 4; ++ks) {  // k16 steps within BK=64
            uint32_t afr[2][4], bfr[2][4];
#pragma unroll
            for (int mi = 0; mi < 2; ++mi) {
                int row = wm * 32 + mi * 16 + ((lm & 1) << 3) + lrow;
                int ch  = ks * 2 + (lm >> 1);
                ldsm4(afr[mi][0], afr[mi][1], afr[mi][2], afr[mi][3],
                      as_addr + ((s * 4096 + row * 32 + ((ch ^ lrow) << 2)) << 2));
            }
#pragma unroll
            for (int np = 0; np < 2; ++np) {
                int row = wn * 32 + np * 16 + ((lm >> 1) << 3) + lrow;
                int ch  = ks * 2 + (lm & 1);
                ldsm4(bfr[np][0], bfr[np][1], bfr[np][2], bfr[np][3],
                      bs_addr + ((s * 2048 + row * 32 + ((ch ^ lrow) << 2)) << 2));
            }
#pragma unroll
            for (int mi = 0; mi < 2; ++mi)
#pragma unroll
                for (int nj = 0; nj < 4; ++nj)
                    mma16(acc[mi][nj], afr[mi], bfr[nj >> 1][(nj & 1) * 2], bfr[nj >> 1][(nj & 1) * 2 + 1]);
        }
        if (it + 1 < KIT) { stage(s ^ 1); __syncthreads(); }
    }

    // ---- epilogue ----
    const int r0l = lane >> 2, c0l = (lane & 3) * 2;
#pragma unroll
    for (int mi = 0; mi < 2; ++mi)
#pragma unroll
        for (int nj = 0; nj < 4; ++nj)
#pragma unroll
            for (int e = 0; e < 4; ++e) {
                int r = m0 + wm * 32 + mi * 16 + r0l + ((e >= 2) ? 8 : 0);
                int n = n0 + wn * 32 + nj * 8 + c0l + (e & 1);
                float val = acc[mi][nj][e];
                if (MODE == 0) {
                    int j = r >> 4, b = r & 15;
                    if (n < 1024) {
                        int h = n >> 7, d = n & 127;
                        g_K[(size_t)((b * 8 + h) * 1024 + j) * 128 + d] = __float2half(val);
                    } else {
                        int n2 = n - 1024; int h = n2 >> 7, d = n2 & 127;
                        g_Vt[(size_t)((b * 8 + h) * 128 + d) * 1024 + j] = __float2half(val);
                    }
                } else if (MODE == 1) {
                    int i = r >> 4, b = r & 15;
                    size_t base = (size_t)((b * 8 + (n >> 7)) * 512 + i) * 128 + (n & 127);
                    g_QU[base] = __float2half(val + uu[n]);
                    g_QV[base] = __float2half(val + vv[n]);
                } else if (MODE == 2) {
                    g_P[(size_t)((n >> 7) * 1024 + r) * 128 + (n & 127)] = __float2half(val);
                } else if (MODE == 4) {
                    int j = n - 511 + r;  // rel-shift: S2shift[i][j] = S2[i][511+j-i]
                    if (j >= 0 && j < 1024)
                        g_S2[(size_t)z * 524288 + (size_t)r * 1024 + j] = __float2half(val);
                } else {  // MODE 6
                    dout[(size_t)r * 128 + n] = val;
                    if (writeAux) dout[2097152 + (size_t)r * 128 + n] = val;
                }
            }
}

// ---- fused flash attention (fp16): 64-row CTAs, 128 threads, 2 CTAs/SM ----
// S = QK^T + S2shift, masked online softmax (log2 domain), O = P V.
// P passes from score C-fragments directly into PV A-fragments (layout identity) —
// no smem round-trip. K, V, S2 double-buffered via cp.async.
// Per stage (10240 u32): K at +0 (2 segs x 2048), V at +4096, S2 at +8192 (64 rows).
__global__ void __launch_bounds__(128, 2) flash_k() {
    extern __shared__ uint32_t sm[];
    const uint32_t smb = (uint32_t)__cvta_generic_to_shared(sm);

    const int bh = blockIdx.y;
    const int ix = 7 - blockIdx.x;     // heavy tiles launch first
    const int i0 = ix * 64;
    const int tid = threadIdx.x, lane = tid & 31, w = tid >> 5;  // w in 0..3
    const int lrow = lane & 7, lm = lane >> 3;
    const int r0l = lane >> 2, c0l = (lane & 3) * 2;

    const __half* Qb  = g_QU + (size_t)bh * 65536;
    const __half* Kb  = g_K  + (size_t)bh * 131072;
    const __half* Vb  = g_Vt + (size_t)bh * 131072;
    const __half* S2b = g_S2 + (size_t)bh * 524288;

    uint32_t qf[8][4];

    // ---- Q fragments via smem staging (single 64-row pass into stage-0 K region) ----
#pragma unroll
    for (int t = 0; t < 8; ++t) {
        int idx = tid + t * 128;
        int row = idx >> 4, c16 = idx & 15;
        int seg = c16 >> 3, ch = c16 & 7;
        uint4 v = *(const uint4*)(Qb + (size_t)(i0 + row) * 128 + c16 * 8);
        *(uint4*)&sm[seg * 2048 + row * 32 + ((ch ^ (row & 7)) << 2)] = v;
    }
    __syncthreads();
    {
        int wr = w * 16;
#pragma unroll
        for (int ks = 0; ks < 8; ++ks) {
            int row = wr + ((lm & 1) << 3) + lrow;
            int seg = ks >> 2, ch = (ks & 3) * 2 + (lm >> 1);
            ldsm4(qf[ks][0], qf[ks][1], qf[ks][2], qf[ks][3],
                  smb + ((seg * 2048 + row * 32 + ((ch ^ lrow) << 2)) << 2));
        }
    }
    __syncthreads();

    // cp.async prefetch of one jt tile (K 16KB + V 16KB + S2 8KB) into stage s
    auto pref = [&](int jt, int s) {
        int j0 = jt * 64;
        int sb = s * 10240;
#pragma unroll
        for (int t = 0; t < 8; ++t) {
            int idx = tid + t * 128;
            int row = idx >> 4, c16 = idx & 15;
            int seg = c16 >> 3, ch = c16 & 7;
            cpa16(smb + ((sb + seg * 2048 + row * 32 + ((ch ^ (row & 7)) << 2)) << 2),
                  Kb + (size_t)(j0 + row) * 128 + c16 * 8);
        }
#pragma unroll
        for (int t = 0; t < 8; ++t) {
            int idx = tid + t * 128;
            int row = idx >> 3, ch = idx & 7;
            cpa16(smb + ((sb + 4096 + row * 32 + ((ch ^ (row & 7)) << 2)) << 2),
                  Vb + (size_t)row * 1024 + j0 + ch * 8);
        }
#pragma unroll
        for (int t = 0; t < 4; ++t) {
            int idx = tid + t * 128;
            int row = idx >> 3, ch = idx & 7;
            cpa16(smb + ((sb + 8192 + row * 32 + ((ch ^ (row & 7)) << 2)) << 2),
                  S2b + (size_t)(i0 + row) * 1024 + j0 + ch * 8);
        }
    };

    float of[16][4];
#pragma unroll
    for (int a = 0; a < 16; ++a)
#pragma unroll
        for (int e = 0; e < 4; ++e) of[a][e] = 0.f;
    float mrow0 = -1e30f, mrow1 = -1e30f;    // log2-domain running max
    float lrow0 = 0.f, lrow1 = 0.f;

    const int gi0 = i0 + w * 16 + r0l;
    const int gi1 = gi0 + 8;
    const int lr0 = w * 16 + r0l, lr1 = lr0 + 8;  // local rows in sS2 (0..63)
    const int njt = ix + 9;       // covers j <= i0+63+512

    pref(0, 0); cp_commit();

    for (int jt = 0; jt < njt; ++jt) {
        const int s = jt & 1;
        int j0 = jt * 64;
        if (jt + 1 < njt) { pref(jt + 1, s ^ 1); cp_commit(); cp_wait<1>(); }
        else cp_wait<0>();
        __syncthreads();
        const int sb = s * 10240;

        // scores: S = Q K^T (16 x 64 per warp)
        float sacc[8][4];
#pragma unroll
        for (int a = 0; a < 8; ++a)
#pragma unroll
            for (int e = 0; e < 4; ++e) sacc[a][e] = 0.f;
#pragma unroll
        for (int ks = 0; ks < 8; ++ks) {
            uint32_t bfr[4][4];
#pragma unroll
            for (int nb = 0; nb < 4; ++nb) {
                int row = nb * 16 + ((lm >> 1) << 3) + lrow;
                int seg = ks >> 2, ch = (ks & 3) * 2 + (lm & 1);
                ldsm4(bfr[nb][0], bfr[nb][1], bfr[nb][2], bfr[nb][3],
                      smb + ((sb + seg * 2048 + row * 32 + ((ch ^ lrow) << 2)) << 2));
            }
#pragma unroll
            for (int nf = 0; nf < 8; ++nf)
                mma16(sacc[nf], qf[ks], bfr[nf >> 1][(nf & 1) * 2], bfr[nf >> 1][(nf & 1) * 2 + 1]);
        }

        // add shifted position scores (smem), mask, scale into log2 domain, online softmax
        float mnew0 = mrow0, mnew1 = mrow1;
#pragma unroll
        for (int nf = 0; nf < 8; ++nf) {
            int jc = j0 + nf * 8 + c0l;
            uint32_t u0 = sm[sb + 8192 + lr0 * 32 + ((nf ^ r0l) << 2) + (lane & 3)];
            uint32_t u1 = sm[sb + 8192 + lr1 * 32 + ((nf ^ r0l) << 2) + (lane & 3)];
            float2 p0 = __half22float2(*reinterpret_cast<__half2*>(&u0));
            float2 p1 = __half22float2(*reinterpret_cast<__half2*>(&u1));
            float s00 = (sacc[nf][0] + p0.x) * SCALE2;
            float s01 = (sacc[nf][1] + p0.y) * SCALE2;
            float s10 = (sacc[nf][2] + p1.x) * SCALE2;
            float s11 = (sacc[nf][3] + p1.y) * SCALE2;
            sacc[nf][0] = (jc     <= gi0 + 512) ? s00 : -1e30f;
            sacc[nf][1] = (jc + 1 <= gi0 + 512) ? s01 : -1e30f;
            sacc[nf][2] = (jc     <= gi1 + 512) ? s10 : -1e30f;
            sacc[nf][3] = (jc + 1 <= gi1 + 512) ? s11 : -1e30f;
            mnew0 = fmaxf(mnew0, fmaxf(sacc[nf][0], sacc[nf][1]));
            mnew1 = fmaxf(mnew1, fmaxf(sacc[nf][2], sacc[nf][3]));
        }
#pragma unroll
        for (int d = 1; d < 4; d <<= 1) {
            mnew0 = fmaxf(mnew0, __shfl_xor_sync(0xffffffffu, mnew0, d));
            mnew1 = fmaxf(mnew1, __shfl_xor_sync(0xffffffffu, mnew1, d));
        }
        float fs0 = exp2f(mrow0 - mnew0);
        float fs1 = exp2f(mrow1 - mnew1);
        mrow0 = mnew0; mrow1 = mnew1;
        float ps0 = 0.f, ps1 = 0.f;
#pragma unroll
        for (int nf = 0; nf < 8; ++nf) {
            sacc[nf][0] = exp2f(sacc[nf][0] - mnew0);
            sacc[nf][1] = exp2f(sacc[nf][1] - mnew0);
            sacc[nf][2] = exp2f(sacc[nf][2] - mnew1);
            sacc[nf][3] = exp2f(sacc[nf][3] - mnew1);
            ps0 += sacc[nf][0] + sacc[nf][1];
            ps1 += sacc[nf][2] + sacc[nf][3];
        }
#pragma unroll
        for (int d = 1; d < 4; d <<= 1) {
            ps0 += __shfl_xor_sync(0xffffffffu, ps0, d);
            ps1 += __shfl_xor_sync(0xffffffffu, ps1, d);
        }
        lrow0 = lrow0 * fs0 + ps0;
        lrow1 = lrow1 * fs1 + ps1;
#pragma unroll
        for (int nf = 0; nf < 16; ++nf) {
            of[nf][0] *= fs0; of[nf][1] *= fs0;
            of[nf][2] *= fs1; of[nf][3] *= fs1;
        }

        // O += P V^T — P A-fragments built directly from score C-fragments
        // (m16n8k16 layout identity), no smem round-trip.
#pragma unroll
        for (int ks = 0; ks < 4; ++ks) {
            uint32_t pa[4];
            pa[0] = f2h2(sacc[2 * ks][0],     sacc[2 * ks][1]);
            pa[1] = f2h2(sacc[2 * ks][2],     sacc[2 * ks][3]);
            pa[2] = f2h2(sacc[2 * ks + 1][0], sacc[2 * ks + 1][1]);
            pa[3] = f2h2(sacc[2 * ks + 1][2], sacc[2 * ks + 1][3]);
#pragma unroll
            for (int nb = 0; nb < 8; ++nb) {
                uint32_t bv[4];
                int rowb = nb * 16 + ((lm >> 1) << 3) + lrow;
                int chb  = ks * 2 + (lm & 1);
                ldsm4(bv[0], bv[1], bv[2], bv[3],
                      smb + ((sb + 4096 + rowb * 32 + ((chb ^ lrow) << 2)) << 2));
                mma16(of[nb * 2],     pa, bv[0], bv[1]);
                mma16(of[nb * 2 + 1], pa, bv[2], bv[3]);
            }
        }
        __syncthreads();
    }

    // normalize + write O (fp16)
    float inv0 = 1.f / lrow0, inv1 = 1.f / lrow1;
    int b = bh >> 3, h = bh & 7;
#pragma unroll
    for (int nf = 0; nf < 16; ++nf) {
        int d = nf * 8 + c0l;
        *(uint32_t*)&g_O[(size_t)(gi0 * 16 + b) * 1024 + h * 128 + d] = f2h2(of[nf][0] * inv0, of[nf][1] * inv0);
        *(uint32_t*)&g_O[(size_t)(gi1 * 16 + b) * 1024 + h * 128 + d] = f2h2(of[nf][2] * inv1, of[nf][3] * inv1);
    }
}

extern "C" void kernel_launch(void* const* d_in, const int* in_sizes, int n_in,
                              void* d_out, int out_size) {
    const float* inputs = (const float*)d_in[0];
    const float* memory = (const float*)d_in[1];
    const float* w_kv   = (const float*)d_in[2];
    const float* w_q    = (const float*)d_in[3];
    const float* w_p    = (const float*)d_in[4];
    const float* w_out  = (const float*)d_in[5];
    const float* u      = (const float*)d_in[6];
    const float* v      = (const float*)d_in[7];
    float* out = (float*)d_out;

    int writeAux = (out_size >= 3 * 1048576) ? 1 : 0;

    // smem: 2 stages x 40KB = 81920 B
    cudaFuncSetAttribute(flash_k, cudaFuncAttributeMaxDynamicSharedMemorySize, 81920);

    // prep: PE table + fp16 operand conversion + middle-third output copy
    prep_k<<<512, 256>>>(inputs, memory, w_kv, w_q, w_p, w_out, out, writeAux);
    // kv proj: M=16384, N=2048, K=128
    gemm_k<0><<<dim3(32, 128, 1), 256>>>(nullptr, nullptr, nullptr, 0);
    // q proj: M=8192, N=1024, K=128
    gemm_k<1><<<dim3(16, 64, 1), 256>>>(u, v, nullptr, 0);
    // p proj: M=1024, N=1024, K=128
    gemm_k<2><<<dim3(16, 8, 1), 256>>>(nullptr, nullptr, nullptr, 0);
    // position scores (shifted epilogue): M=512, N=1024, K=128, z=128
    gemm_k<4><<<dim3(16, 4, 128), 256>>>(nullptr, nullptr, nullptr, 0);
    // fused flash attention: 64-row CTAs, 128 threads, 2 CTAs/SM
    flash_k<<<dim3(8, 128), 128, 81920>>>();
    // out proj: M=8192, N=128, K=1024
    gemm_k<6><<<dim3(2, 64), 256>>>(nullptr, nullptr, out, writeAux);
}